// round 5
// baseline (speedup 1.0000x reference)
#include <cuda_runtime.h>
#include <cuda_bf16.h>
#include <math.h>
#include <stdint.h>

#define N_NODES 512
#define TT 128
#define NE 4096
#define C0 64
#define C1 128
#define C2 128
#define EMB 256
#define NG 8
#define EPSV 1e-5f
#define QMAX 16319.f

// ---------------- scratch (device globals; no allocs allowed) ----------------
__device__ float g_y1[N_NODES*TT*C0];            // conv1 raw out
__device__ float g_y2[N_NODES*122*C1];
__device__ float g_gbuf[NG*30*C1];
__device__ float g_y3[NG*28*C2];
__device__ float g_pe[N_NODES*C0];
__device__ float g_A[NG*64*64];
__device__ int   g_deg[N_NODES];
__device__ float g_s1[C0], g_sq1[C0];
__device__ float g_s2[C1], g_sq2[C1];
__device__ float g_mu3[C2], g_rs3[C2];
__device__ float g_sA2f[N_NODES];                // per-node max of h2
__device__ float g_sB2[C1];                      // per-row scale of W2

// bf16 split buffers
__device__ __nv_bfloat16 g_Ash[NG*64*64],        g_Asl[NG*64*64];
__device__ __nv_bfloat16 g_h0h[N_NODES*TT*C0],   g_h0l[N_NODES*TT*C0];
__device__ __nv_bfloat16 g_agg0h[N_NODES*TT*C0], g_agg0l[N_NODES*TT*C0];
__device__ __nv_bfloat16 g_h1h[N_NODES*TT*EMB],  g_h1l[N_NODES*TT*EMB];
__device__ __nv_bfloat16 g_agg1h[N_NODES*TT*EMB],g_agg1l[N_NODES*TT*EMB];
__device__ __nv_bfloat16 g_h2h[N_NODES*TT*EMB],  g_h2l[N_NODES*TT*EMB];
__device__ __nv_bfloat16 g_Wg1th[EMB*C0],  g_Wg1tl[EMB*C0];
__device__ __nv_bfloat16 g_Wg2th[EMB*EMB], g_Wg2tl[EMB*EMB];

// int8 slices for conv2
__device__ char g_h2q_hi[N_NODES*TT*EMB], g_h2q_lo[N_NODES*TT*EMB];
__device__ char g_W2q_hi[C1*7*EMB],       g_W2q_lo[C1*7*EMB];   // [128][1792]

// ---------------- helpers ----------------
__device__ __forceinline__ uint32_t smem_u32(const void* p) {
    uint32_t a;
    asm("{ .reg .u64 t; cvta.to.shared.u64 t, %1; cvt.u32.u64 %0, t; }" : "=r"(a) : "l"(p));
    return a;
}
#define CP16(dst, src) asm volatile("cp.async.cg.shared.global [%0], [%1], 16;" :: "r"(dst), "l"(src))
#define CP_COMMIT()    asm volatile("cp.async.commit_group;" ::: "memory")
#define CP_WAIT1()     asm volatile("cp.async.wait_group 1;" ::: "memory")
#define CP_WAIT0()     asm volatile("cp.async.wait_group 0;" ::: "memory")
#define LDSM_X4(r0, r1, r2, r3, addr) \
    asm volatile("ldmatrix.sync.aligned.m8n8.x4.shared.b16 {%0,%1,%2,%3}, [%4];" \
        : "=r"(r0), "=r"(r1), "=r"(r2), "=r"(r3) : "r"(addr))
#define LDSM_X4T(r0, r1, r2, r3, addr) \
    asm volatile("ldmatrix.sync.aligned.m8n8.x4.trans.shared.b16 {%0,%1,%2,%3}, [%4];" \
        : "=r"(r0), "=r"(r1), "=r"(r2), "=r"(r3) : "r"(addr))
#define MMA16816(d, a, b) \
    asm volatile("mma.sync.aligned.m16n8k16.row.col.f32.bf16.bf16.f32 " \
        "{%0,%1,%2,%3}, {%4,%5,%6,%7}, {%8,%9}, {%0,%1,%2,%3};" \
        : "+f"((d)[0]), "+f"((d)[1]), "+f"((d)[2]), "+f"((d)[3]) \
        : "r"((a)[0]), "r"((a)[1]), "r"((a)[2]), "r"((a)[3]), "r"((b)[0]), "r"((b)[1]))
#define MMAI8(d, a, b) \
    asm volatile("mma.sync.aligned.m16n8k32.row.col.s32.s8.s8.s32 " \
        "{%0,%1,%2,%3}, {%4,%5,%6,%7}, {%8,%9}, {%0,%1,%2,%3};" \
        : "+r"((d)[0]), "+r"((d)[1]), "+r"((d)[2]), "+r"((d)[3]) \
        : "r"((a)[0]), "r"((a)[1]), "r"((a)[2]), "r"((a)[3]), "r"((b)[0]), "r"((b)[1]))

__device__ __forceinline__ void split_store(__nv_bfloat16* H, __nv_bfloat16* L,
                                            long long idx, float v0, float v1) {
    __nv_bfloat16 h0 = __float2bfloat16(v0), h1 = __float2bfloat16(v1);
    __nv_bfloat162 hv; hv.x = h0; hv.y = h1;
    __nv_bfloat162 lv;
    lv.x = __float2bfloat16(v0 - __bfloat162float(h0));
    lv.y = __float2bfloat16(v1 - __bfloat162float(h1));
    *(__nv_bfloat162*)&H[idx] = hv;
    *(__nv_bfloat162*)&L[idx] = lv;
}

// ---------------- setup kernels ----------------
__global__ void k_zero() {
    int i = blockIdx.x*256 + threadIdx.x;
    if (i < NG*64*64) g_A[i] = 0.f;
    if (i < N_NODES)  { g_deg[i] = 0; g_sA2f[i] = 0.f; }
    if (i < C0) { g_s1[i]=0.f; g_sq1[i]=0.f; }
    if (i < C1) { g_s2[i]=0.f; g_sq2[i]=0.f; }
    if (i < NG*30*C1) g_gbuf[i] = 0.f;
}

__global__ void k_deg(const int* __restrict__ ei) {
    int e = blockIdx.x*256 + threadIdx.x;
    if (e < NE) atomicAdd(&g_deg[ei[NE + e]], 1);
}

__global__ void k_adj(const int* __restrict__ ei) {
    int i = blockIdx.x*256 + threadIdx.x;
    if (i < NE) {
        int s = ei[i], d = ei[NE + i];
        float nr = rsqrtf((float)(g_deg[s]+1)) * rsqrtf((float)(g_deg[d]+1));
        int g = d >> 6;
        atomicAdd(&g_A[(g<<12) + ((d&63)<<6) + (s&63)], nr);
    } else if (i < NE + N_NODES) {
        int n = i - NE;
        float di = 1.f / (float)(g_deg[n]+1);
        atomicAdd(&g_A[((n>>6)<<12) + ((n&63)<<6) + (n&63)], di);
    }
}

__global__ void k_asplit() {
    int i = blockIdx.x*256 + threadIdx.x;
    float v = g_A[i];
    __nv_bfloat16 h = __float2bfloat16(v);
    g_Ash[i] = h;
    g_Asl[i] = __float2bfloat16(v - __bfloat162float(h));
}

__global__ void k_wsplit(const float* __restrict__ W, __nv_bfloat16* __restrict__ hi,
                         __nv_bfloat16* __restrict__ lo, int K, int N) {
    int i = blockIdx.x*256 + threadIdx.x;
    if (i >= K*N) return;
    int n = i / K, k = i - n*K;
    float v = W[k*N + n];
    __nv_bfloat16 h = __float2bfloat16(v);
    hi[i] = h;
    lo[i] = __float2bfloat16(v - __bfloat162float(h));
}

// W2 [1792][128] -> int8 2-slice K-major [n][1792] + per-row scale
__global__ void k_wquant(const float* __restrict__ W2) {
    __shared__ float red[256];
    int n = blockIdx.x, tid = threadIdx.x;
    float w[7]; float m = 0.f;
    #pragma unroll
    for (int it = 0; it < 7; ++it) {
        int k = it*256 + tid;
        w[it] = W2[k*128 + n];
        m = fmaxf(m, fabsf(w[it]));
    }
    red[tid] = m; __syncthreads();
    for (int s = 128; s; s >>= 1) {
        if (tid < s) red[tid] = fmaxf(red[tid], red[tid+s]);
        __syncthreads();
    }
    float mx = red[0];
    float invs = mx > 1e-30f ? QMAX/mx : 0.f;
    if (tid == 0) g_sB2[n] = mx * (1.f/QMAX);
    #pragma unroll
    for (int it = 0; it < 7; ++it) {
        int k = it*256 + tid;
        int q = __float2int_rn(w[it]*invs);
        int hi = (q + 64) >> 7;
        g_W2q_hi[n*1792 + k] = (char)hi;
        g_W2q_lo[n*1792 + k] = (char)(q - (hi << 7));
    }
}

// h2 bf16 pair -> int8 2-slice with per-node scale
__global__ void k_h2quant() {
    long long base = ((long long)blockIdx.x*256 + threadIdx.x) * 8;
    int node = (int)(base >> 15);
    float mx = g_sA2f[node];
    float invs = mx > 1e-30f ? QMAX/mx : 0.f;
    uint4 hv = *(const uint4*)(g_h2h + base);
    uint4 lv = *(const uint4*)(g_h2l + base);
    const unsigned* hw = (const unsigned*)&hv;
    const unsigned* lw = (const unsigned*)&lv;
    unsigned hib[2] = {0,0}, lob[2] = {0,0};
    #pragma unroll
    for (int e = 0; e < 8; ++e) {
        unsigned hb = (hw[e>>1] >> ((e&1)*16)) & 0xffffu;
        unsigned lb = (lw[e>>1] >> ((e&1)*16)) & 0xffffu;
        float v = __uint_as_float(hb << 16) + __uint_as_float(lb << 16);
        int q = __float2int_rn(v * invs);
        int hi = (q + 64) >> 7;
        int lo = q - (hi << 7);
        hib[e>>2] |= (unsigned)(hi & 255) << ((e&3)*8);
        lob[e>>2] |= (unsigned)(lo & 255) << ((e&3)*8);
    }
    *(uint2*)(g_h2q_hi + base) = make_uint2(hib[0], hib[1]);
    *(uint2*)(g_h2q_lo + base) = make_uint2(lob[0], lob[1]);
}

__global__ void k_pe(const float* __restrict__ pos, const float* __restrict__ Wp1,
                     const float* __restrict__ bp1, const float* __restrict__ Wp2,
                     const float* __restrict__ bp2) {
    __shared__ float t1[64];
    int n = blockIdx.x, j = threadIdx.x;
    float p0 = pos[n*3], p1 = pos[n*3+1], p2 = pos[n*3+2];
    t1[j] = fmaxf(p0*Wp1[j] + p1*Wp1[64+j] + p2*Wp1[128+j] + bp1[j], 0.f);
    __syncthreads();
    float s = bp2[j];
    #pragma unroll 8
    for (int k = 0; k < 64; ++k) s += t1[k]*Wp2[k*64 + j];
    g_pe[n*64 + j] = s;
}

__global__ void k_conv1(const float* __restrict__ x, const float* __restrict__ W1) {
    __shared__ float sx[70];
    __shared__ float red[256];
    int b = blockIdx.x;
    int n = b >> 1;
    int t0 = (b & 1) * 64;
    int tid = threadIdx.x;
    if (tid < 70) {
        int t = t0 - 3 + tid;
        sx[tid] = (t >= 0 && t < TT) ? x[n*TT + t] : 0.f;
    }
    __syncthreads();
    int c = tid & 63, r0 = tid >> 6;
    float w[7];
    #pragma unroll
    for (int k = 0; k < 7; ++k) w[k] = W1[k*64 + c];
    float ls = 0.f, lq = 0.f;
    for (int rr = r0; rr < 64; rr += 4) {
        float y = 0.f;
        #pragma unroll
        for (int k = 0; k < 7; ++k) y += sx[rr + k] * w[k];
        g_y1[(b*64 + rr)*64 + c] = y;
        ls += y; lq += y*y;
    }
    red[tid] = ls; __syncthreads();
    if (tid < 64) atomicAdd(&g_s1[c], red[tid]+red[tid+64]+red[tid+128]+red[tid+192]);
    __syncthreads();
    red[tid] = lq; __syncthreads();
    if (tid < 64) atomicAdd(&g_sq1[c], red[tid]+red[tid+64]+red[tid+128]+red[tid+192]);
}

__global__ void k_bn1pe(const float* __restrict__ g1w, const float* __restrict__ b1w) {
    int i4 = blockIdx.x*256 + threadIdx.x;
    int base = i4 * 4;
    int c0 = base & 63;
    int n = base >> 13;
    float4 v = *(float4*)&g_y1[base];
    float vv[4] = {v.x, v.y, v.z, v.w};
    #pragma unroll
    for (int j = 0; j < 4; ++j) {
        int c = c0 + j;
        float mu  = g_s1[c]  * (1.f/65536.f);
        float var = g_sq1[c] * (1.f/65536.f) - mu*mu;
        float a = g1w[c] * rsqrtf(var + EPSV);
        float bb = b1w[c] - mu*a;
        vv[j] = fmaxf(a*vv[j] + bb, 0.f) + g_pe[n*64 + c];
    }
    split_store(g_h0h, g_h0l, base,   vv[0], vv[1]);
    split_store(g_h0h, g_h0l, base+2, vv[2], vv[3]);
}

// ---------------- fp32 SIMT GEMM (conv3 only) ----------------
__global__ void k_gemm(const float* __restrict__ Aall, const float* __restrict__ Ball,
                       float* __restrict__ Call,
                       int M, int N, int K, int Tout, int Tin, int rowC)
{
    const float* A = Aall;
    const float* B = Ball;

    __shared__ __align__(16) float As[16][68];
    __shared__ __align__(16) float Bs[16][68];

    int tid = threadIdx.x;
    int tx = tid & 15, ty = tid >> 4;
    int m0 = blockIdx.y * 64;
    int n0 = blockIdx.x * 64;

    int abase[4]; bool aok[4];
    #pragma unroll
    for (int p = 0; p < 4; ++p) {
        int row = m0 + p*16 + (tid >> 4);
        aok[p] = (row < M);
        abase[p] = aok[p] ? ((row / Tout) * Tin + (row % Tout)) * rowC : 0;
    }
    int akk = tid & 15;

    float acc[4][4] = {};

    for (int k0 = 0; k0 < K; k0 += 16) {
        #pragma unroll
        for (int p = 0; p < 4; ++p) {
            float v = aok[p] ? A[abase[p] + k0 + akk] : 0.f;
            As[akk][p*16 + (tid >> 4)] = v;
        }
        #pragma unroll
        for (int p = 0; p < 4; ++p) {
            int kk = p*4 + (tid >> 6);
            Bs[kk][tid & 63] = B[(k0 + kk) * N + n0 + (tid & 63)];
        }
        __syncthreads();
        #pragma unroll
        for (int kk = 0; kk < 16; ++kk) {
            float4 av = *(const float4*)&As[kk][ty*4];
            float4 bv = *(const float4*)&Bs[kk][tx*4];
            float a_[4] = {av.x, av.y, av.z, av.w};
            float b_[4] = {bv.x, bv.y, bv.z, bv.w};
            #pragma unroll
            for (int i = 0; i < 4; ++i)
                #pragma unroll
                for (int j = 0; j < 4; ++j)
                    acc[i][j] += a_[i] * b_[j];
        }
        __syncthreads();
    }

    #pragma unroll
    for (int i = 0; i < 4; ++i) {
        int row = m0 + ty*4 + i;
        if (row >= M) continue;
        #pragma unroll
        for (int j = 0; j < 4; ++j) {
            int col = n0 + tx*4 + j;
            Call[(long long)row * N + col] = acc[i][j];
        }
    }
}

// ---------------- TC aggregation: O = A(64x64) @ H(64xF) per graph -----------
#define ASTR 72
#define HSTR 264
#define AGG_SMEM (2*64*ASTR*2 + 2*64*HSTR*2)

__global__ void __launch_bounds__(256, 1)
k_agg_tc(const __nv_bfloat16* __restrict__ Hh, const __nv_bfloat16* __restrict__ Hl,
         __nv_bfloat16* __restrict__ Oh, __nv_bfloat16* __restrict__ Ol, int F)
{
    extern __shared__ char dsm[];
    uint32_t sAh = smem_u32(dsm);
    uint32_t sAl = sAh + 64*ASTR*2;
    uint32_t sHh = sAl + 64*ASTR*2;
    uint32_t sHl = sHh + 64*HSTR*2;

    int g = blockIdx.y;
    int n0 = blockIdx.x * 256;
    int tid = threadIdx.x, lane = tid & 31, wid = tid >> 5;

    const char* Agh = (const char*)(g_Ash + g*4096);
    const char* Agl = (const char*)(g_Asl + g*4096);
    #pragma unroll
    for (int it = 0; it < 2; ++it) {
        int sid = it*256 + tid;
        int row = sid >> 3, seg = (sid & 7) * 8;
        CP16(sAh + (row*ASTR + seg)*2, Agh + (row*64 + seg)*2);
        CP16(sAl + (row*ASTR + seg)*2, Agl + (row*64 + seg)*2);
    }
    long long hbase = (long long)(g*64) * F + n0;
    #pragma unroll
    for (int it = 0; it < 8; ++it) {
        int sid = it*256 + tid;
        int row = sid >> 5, seg = (sid & 31) * 8;
        long long go = (hbase + (long long)row*F + seg) * 2;
        CP16(sHh + (row*HSTR + seg)*2, (const char*)Hh + go);
        CP16(sHl + (row*HSTR + seg)*2, (const char*)Hl + go);
    }
    CP_COMMIT();
    CP_WAIT0();
    __syncthreads();

    float acc[4][4][4] = {};
    int nw = wid * 32;
    uint32_t arow = lane & 15, ahi = (lane >> 4) * 8;

    #pragma unroll
    for (int kk = 0; kk < 4; ++kk) {
        uint32_t ah[4][4], al[4][4], bh[4][2], bl[4][2];
        uint32_t acol = kk*16 + ahi;
        #pragma unroll
        for (int i = 0; i < 4; ++i) {
            LDSM_X4(ah[i][0], ah[i][1], ah[i][2], ah[i][3],
                    sAh + ((i*16 + arow)*ASTR + acol)*2);
            LDSM_X4(al[i][0], al[i][1], al[i][2], al[i][3],
                    sAl + ((i*16 + arow)*ASTR + acol)*2);
        }
        uint32_t brow = kk*16 + (lane & 15);
        #pragma unroll
        for (int jp = 0; jp < 2; ++jp) {
            uint32_t bcol = nw + jp*16 + ahi;
            uint32_t t0, t1, t2, t3;
            LDSM_X4T(t0, t1, t2, t3, sHh + (brow*HSTR + bcol)*2);
            bh[jp*2][0] = t0; bh[jp*2][1] = t1; bh[jp*2+1][0] = t2; bh[jp*2+1][1] = t3;
            LDSM_X4T(t0, t1, t2, t3, sHl + (brow*HSTR + bcol)*2);
            bl[jp*2][0] = t0; bl[jp*2][1] = t1; bl[jp*2+1][0] = t2; bl[jp*2+1][1] = t3;
        }
        #pragma unroll
        for (int i = 0; i < 4; ++i)
            #pragma unroll
            for (int j = 0; j < 4; ++j) {
                MMA16816(acc[i][j], ah[i], bh[j]);
                MMA16816(acc[i][j], ah[i], bl[j]);
                MMA16816(acc[i][j], al[i], bh[j]);
            }
    }

    int rb = lane >> 2;
    int cb = n0 + nw + (lane & 3)*2;
    #pragma unroll
    for (int i = 0; i < 4; ++i)
        #pragma unroll
        for (int j = 0; j < 4; ++j)
            #pragma unroll
            for (int half = 0; half < 2; ++half) {
                int row = i*16 + rb + half*8;
                long long idx = (long long)(g*64 + row) * F + cb + j*8;
                split_store(Oh, Ol, idx, acc[i][j][half*2], acc[i][j][half*2+1]);
            }
}

// ---------------- bf16-split tensor-core GEMM via mma.sync --------------------
#define KC 32
#define LDS_STRIDE 40
#define ARR_BYTES (128*LDS_STRIDE*2)
#define STAGE_BYTES (4*ARR_BYTES)

__global__ void __launch_bounds__(256, 1)
k_gemm_tc(const __nv_bfloat16* __restrict__ Ah, const __nv_bfloat16* __restrict__ Al,
          const __nv_bfloat16* __restrict__ Bh, const __nv_bfloat16* __restrict__ Bl,
          const float* __restrict__ bias,
          __nv_bfloat16* __restrict__ Chi, __nv_bfloat16* __restrict__ Clo,
          float* __restrict__ nmax,
          int K, int ldc)
{
    extern __shared__ char dsm[];
    uint32_t sbase = smem_u32(dsm);
    int tid = threadIdx.x, lane = tid & 31, wid = tid >> 5;
    int m0 = blockIdx.y * 128, n0 = blockIdx.x * 128;

    long long gA[2], gB[2];
    uint32_t so[2];
    #pragma unroll
    for (int p = 0; p < 2; ++p) {
        int row = p*64 + (tid >> 2);
        int seg = tid & 3;
        gA[p] = (long long)(m0 + row) * K + seg*8;
        gB[p] = (long long)(n0 + row) * K + seg*8;
        so[p] = (uint32_t)(row*LDS_STRIDE + seg*8) * 2;
    }

    int wm = wid & 1, wn = wid >> 1;
    uint32_t aoff = (uint32_t)((wm*64 + (lane & 15))*LDS_STRIDE + (lane >> 4)*8) * 2;
    uint32_t boff = (uint32_t)((wn*32 + ((lane >> 4) & 1)*8 + (lane & 7))*LDS_STRIDE
                               + ((lane >> 3) & 1)*8) * 2;

    float acc[4][4][4] = {};

    int nc = K >> 5;
    {
        uint32_t st = sbase;
        #pragma unroll
        for (int p = 0; p < 2; ++p) {
            CP16(st +              so[p], (const char*)Ah + gA[p]*2);
            CP16(st + ARR_BYTES  + so[p], (const char*)Al + gA[p]*2);
            CP16(st + 2*ARR_BYTES+ so[p], (const char*)Bh + gB[p]*2);
            CP16(st + 3*ARR_BYTES+ so[p], (const char*)Bl + gB[p]*2);
        }
    }
    CP_COMMIT();

    for (int c = 0; c < nc; ++c) {
        if (c + 1 < nc) {
            uint32_t st = sbase + ((c+1) & 1)*STAGE_BYTES;
            long long k0 = (long long)(c+1)*KC;
            #pragma unroll
            for (int p = 0; p < 2; ++p) {
                CP16(st +              so[p], (const char*)Ah + (gA[p]+k0)*2);
                CP16(st + ARR_BYTES  + so[p], (const char*)Al + (gA[p]+k0)*2);
                CP16(st + 2*ARR_BYTES+ so[p], (const char*)Bh + (gB[p]+k0)*2);
                CP16(st + 3*ARR_BYTES+ so[p], (const char*)Bl + (gB[p]+k0)*2);
            }
        }
        CP_COMMIT();
        CP_WAIT1();
        __syncthreads();

        uint32_t st = sbase + (c & 1)*STAGE_BYTES;
        uint32_t aAh = st + aoff,               aAl = st + ARR_BYTES   + aoff;
        uint32_t aBh = st + 2*ARR_BYTES + boff, aBl = st + 3*ARR_BYTES + boff;

        #pragma unroll
        for (int k16 = 0; k16 < 2; ++k16) {
            uint32_t kb = k16 * 32;
            uint32_t ah[4][4], al[4][4], bh[4][2], bl[4][2];
            #pragma unroll
            for (int i = 0; i < 4; ++i) {
                LDSM_X4(ah[i][0], ah[i][1], ah[i][2], ah[i][3], aAh + kb + i*(16*LDS_STRIDE*2));
                LDSM_X4(al[i][0], al[i][1], al[i][2], al[i][3], aAl + kb + i*(16*LDS_STRIDE*2));
            }
            #pragma unroll
            for (int jj = 0; jj < 2; ++jj) {
                uint32_t t0, t1, t2, t3;
                LDSM_X4(t0, t1, t2, t3, aBh + kb + jj*(16*LDS_STRIDE*2));
                bh[jj*2][0] = t0; bh[jj*2][1] = t1; bh[jj*2+1][0] = t2; bh[jj*2+1][1] = t3;
                LDSM_X4(t0, t1, t2, t3, aBl + kb + jj*(16*LDS_STRIDE*2));
                bl[jj*2][0] = t0; bl[jj*2][1] = t1; bl[jj*2+1][0] = t2; bl[jj*2+1][1] = t3;
            }
            #pragma unroll
            for (int i = 0; i < 4; ++i)
                #pragma unroll
                for (int j = 0; j < 4; ++j) {
                    MMA16816(acc[i][j], ah[i], bh[j]);
                    MMA16816(acc[i][j], ah[i], bl[j]);
                    MMA16816(acc[i][j], al[i], bh[j]);
                }
        }
        __syncthreads();
    }

    float vmax = 0.f;
    int rbase = m0 + wm*64 + (lane >> 2);
    int cbase = n0 + wn*32 + (lane & 3)*2;
    #pragma unroll
    for (int i = 0; i < 4; ++i) {
        #pragma unroll
        for (int j = 0; j < 4; ++j) {
            int gc = cbase + j*8;
            #pragma unroll
            for (int half = 0; half < 2; ++half) {
                long long gr = rbase + i*16 + half*8;
                float v0 = fmaxf(acc[i][j][half*2]     + bias[gc],   0.f);
                float v1 = fmaxf(acc[i][j][half*2 + 1] + bias[gc+1], 0.f);
                vmax = fmaxf(vmax, fmaxf(v0, v1));
                split_store(Chi, Clo, gr * ldc + gc, v0, v1);
            }
        }
    }

    if (nmax) {
        __shared__ float smax[8];
        #pragma unroll
        for (int off = 16; off; off >>= 1)
            vmax = fmaxf(vmax, __shfl_xor_sync(0xffffffffu, vmax, off));
        if (lane == 0) smax[wid] = vmax;
        __syncthreads();
        if (tid == 0) {
            float m = smax[0];
            #pragma unroll
            for (int i2 = 1; i2 < 8; ++i2) m = fmaxf(m, smax[i2]);
            atomicMax((int*)&nmax[blockIdx.y], __float_as_int(m));
        }
    }
}

// ---------------- int8 2-slice conv2 (implicit im2col) ------------------------
// y2[m][n] = sA[node(m)] * sB[n] * (16384*hh + 128*mid);  m in 62464, n in 128.
// Block 128x64, 8 warps (64x16), KC=64 int8, double-buffered. BN2 stats fused.
#define I8_STR 80
#define I8_A_BYTES (128*I8_STR)
#define I8_B_BYTES (64*I8_STR)
#define I8_STAGE (2*I8_A_BYTES + 2*I8_B_BYTES)   // 30720

__global__ void __launch_bounds__(256)
k_conv2_i8()
{
    extern __shared__ char dsm[];
    __shared__ float s_sum[64], s_sq[64];
    uint32_t sb = smem_u32(dsm);
    int tid = threadIdx.x, lane = tid & 31, wid = tid >> 5;
    int m0 = blockIdx.y * 128, n0 = blockIdx.x * 64;

    long long baseA[2];
    uint32_t soA[2];
    #pragma unroll
    for (int it = 0; it < 2; ++it) {
        int row = it*64 + (tid >> 2);
        int rg = m0 + row;
        baseA[it] = (long long)((rg/122)*128 + (rg%122))*256 + (tid & 3)*16;
        soA[it] = row*I8_STR + (tid & 3)*16;
    }
    long long baseB = (long long)(n0 + (tid >> 2))*1792 + (tid & 3)*16;
    uint32_t soB = (tid >> 2)*I8_STR + (tid & 3)*16;

    int wm = wid & 1, wn = wid >> 1;
    uint32_t aoffA = (wm*64 + (lane & 15))*I8_STR + (lane >> 4)*16;
    uint32_t boffB = (wn*16 + ((lane >> 4) & 1)*8 + (lane & 7))*I8_STR
                     + ((lane >> 3) & 1)*16;

    int hh[4][2][4] = {}, mid[4][2][4] = {};

    const int nc = 28;   // 1792/64
    {
        uint32_t st = sb;
        #pragma unroll
        for (int it = 0; it < 2; ++it) {
            CP16(st +              soA[it], g_h2q_hi + baseA[it]);
            CP16(st + I8_A_BYTES + soA[it], g_h2q_lo + baseA[it]);
        }
        CP16(st + 2*I8_A_BYTES +              soB, g_W2q_hi + baseB);
        CP16(st + 2*I8_A_BYTES + I8_B_BYTES + soB, g_W2q_lo + baseB);
    }
    CP_COMMIT();

    for (int c = 0; c < nc; ++c) {
        if (c + 1 < nc) {
            uint32_t st = sb + ((c+1) & 1)*I8_STAGE;
            long long k0 = (long long)(c+1)*64;
            #pragma unroll
            for (int it = 0; it < 2; ++it) {
                CP16(st +              soA[it], g_h2q_hi + baseA[it] + k0);
                CP16(st + I8_A_BYTES + soA[it], g_h2q_lo + baseA[it] + k0);
            }
            CP16(st + 2*I8_A_BYTES +              soB, g_W2q_hi + baseB + k0);
            CP16(st + 2*I8_A_BYTES + I8_B_BYTES + soB, g_W2q_lo + baseB + k0);
        }
        CP_COMMIT();
        CP_WAIT1();
        __syncthreads();

        uint32_t st = sb + (c & 1)*I8_STAGE;
        uint32_t aH = st + aoffA, aL = st + I8_A_BYTES + aoffA;
        uint32_t bH = st + 2*I8_A_BYTES + boffB;
        uint32_t bL = bH + I8_B_BYTES;

        #pragma unroll
        for (int step = 0; step < 2; ++step) {
            uint32_t kb = step * 32;
            uint32_t ah[4][4], al[4][4], bhf[2][2], blf[2][2];
            #pragma unroll
            for (int i = 0; i < 4; ++i) {
                LDSM_X4(ah[i][0], ah[i][1], ah[i][2], ah[i][3], aH + kb + i*(16*I8_STR));
                LDSM_X4(al[i][0], al[i][1], al[i][2], al[i][3], aL + kb + i*(16*I8_STR));
            }
            {
                uint32_t t0, t1, t2, t3;
                LDSM_X4(t0, t1, t2, t3, bH + kb);
                bhf[0][0] = t0; bhf[0][1] = t1; bhf[1][0] = t2; bhf[1][1] = t3;
                LDSM_X4(t0, t1, t2, t3, bL + kb);
                blf[0][0] = t0; blf[0][1] = t1; blf[1][0] = t2; blf[1][1] = t3;
            }
            #pragma unroll
            for (int i = 0; i < 4; ++i)
                #pragma unroll
                for (int j = 0; j < 2; ++j) {
                    MMAI8(hh[i][j],  ah[i], bhf[j]);
                    MMAI8(mid[i][j], ah[i], blf[j]);
                    MMAI8(mid[i][j], al[i], bhf[j]);
                }
        }
        __syncthreads();
    }

    if (tid < 64) { s_sum[tid] = 0.f; s_sq[tid] = 0.f; }
    __syncthreads();

    float psum[4] = {}, psq[4] = {};
    int rrow0 = m0 + wm*64 + (lane >> 2);
    int cb = n0 + wn*16 + (lane & 3)*2;
    #pragma unroll
    for (int i = 0; i < 4; ++i) {
        #pragma unroll
        for (int j = 0; j < 2; ++j) {
            int gc = cb + j*8;
            float sb0 = g_sB2[gc], sb1 = g_sB2[gc+1];
            #pragma unroll
            for (int half = 0; half < 2; ++half) {
                int rg = rrow0 + i*16 + half*8;
                float sa = g_sA2f[rg/122] * (1.f/QMAX);
                float v0 = sa*sb0*((float)hh[i][j][half*2]  *16384.f + (float)mid[i][j][half*2]  *128.f);
                float v1 = sa*sb1*((float)hh[i][j][half*2+1]*16384.f + (float)mid[i][j][half*2+1]*128.f);
                *(float2*)&g_y2[(long long)rg*128 + gc] = make_float2(v0, v1);
                psum[j*2]   += v0;  psq[j*2]   += v0*v0;
                psum[j*2+1] += v1;  psq[j*2+1] += v1*v1;
            }
        }
    }
    int lc = wn*16 + (lane & 3)*2;
    #pragma unroll
    for (int j = 0; j < 2; ++j) {
        atomicAdd(&s_sum[lc + j*8],     psum[j*2]);
        atomicAdd(&s_sum[lc + j*8 + 1], psum[j*2+1]);
        atomicAdd(&s_sq[lc + j*8],      psq[j*2]);
        atomicAdd(&s_sq[lc + j*8 + 1],  psq[j*2+1]);
    }
    __syncthreads();
    if (tid < 64)       atomicAdd(&g_s2[n0 + tid],        s_sum[tid]);
    else if (tid < 128) atomicAdd(&g_sq2[n0 + tid - 64],  s_sq[tid - 64]);
}

// ---------------- pool / BN3 / tail ----------------
__global__ void k_pool(const float* __restrict__ g2w, const float* __restrict__ b2w) {
    int c = threadIdx.x;
    int chunk = blockIdx.x;
    int tp = blockIdx.y;
    int g = blockIdx.z;
    float mu  = g_s2[c]  * (1.f/62464.f);
    float var = g_sq2[c] * (1.f/62464.f) - mu*mu;
    float a = g2w[c] * rsqrtf(var + EPSV);
    float bb = b2w[c] - mu*a;
    float acc = 0.f;
    for (int nl = 0; nl < 16; ++nl) {
        int n = g*64 + chunk*16 + nl;
        const float* p = &g_y2[(n*122 + tp*4)*128 + c];
        float s4 = p[0] + p[128] + p[256] + p[384];
        acc += fmaxf(a * (s4 * 0.25f) + bb, 0.f);
    }
    atomicAdd(&g_gbuf[(g*30 + tp)*128 + c], acc * (1.f/64.f));
}

__global__ void k_bn3stats() {
    __shared__ float red[256];
    int tid = threadIdx.x;
    int c = tid & 127, r0 = tid >> 7;
    float ls = 0.f, lq = 0.f;
    for (int r = r0; r < 224; r += 2) { float v = g_y3[r*128 + c]; ls += v; lq += v*v; }
    red[tid] = ls; __syncthreads();
    float ssum = 0.f;
    if (tid < 128) ssum = red[tid] + red[tid+128];
    __syncthreads();
    red[tid] = lq; __syncthreads();
    if (tid < 128) {
        float q = red[tid] + red[tid+128];
        float mu = ssum * (1.f/224.f);
        float var = q * (1.f/224.f) - mu*mu;
        g_mu3[tid] = mu;
        g_rs3[tid] = rsqrtf(var + EPSV);
    }
}

__global__ void k_tail(const float* __restrict__ g3w, const float* __restrict__ b3w,
                       const float* __restrict__ Wd, const float* __restrict__ bd,
                       float* __restrict__ out) {
    __shared__ float gg[896];
    __shared__ float slog[4];
    int b = blockIdx.x, tid = threadIdx.x;
    int c = tid;
    float a = g3w[c] * g_rs3[c];
    float bb = b3w[c] - g_mu3[c]*a;
    #pragma unroll
    for (int tp = 0; tp < 7; ++tp) {
        const float* p = &g_y3[(b*28 + tp*4)*128 + c];
        float s4 = (p[0] + p[128] + p[256] + p[384]) * 0.25f;
        gg[tp*128 + c] = fmaxf(a*s4 + bb, 0.f);
    }
    __syncthreads();
    int w = tid >> 5, lane = tid & 31;
    float s = 0.f;
    for (int i = lane; i < 896; i += 32) s += gg[i] * Wd[i*4 + w];
    #pragma unroll
    for (int off = 16; off; off >>= 1) s += __shfl_xor_sync(0xffffffffu, s, off);
    if (lane == 0) slog[w] = s + bd[w];
    __syncthreads();
    if (tid == 0) {
        float m = fmaxf(fmaxf(slog[0], slog[1]), fmaxf(slog[2], slog[3]));
        float se = expf(slog[0]-m)+expf(slog[1]-m)+expf(slog[2]-m)+expf(slog[3]-m);
        float lse = logf(se);
        #pragma unroll
        for (int j = 0; j < 4; ++j) out[b*4 + j] = slog[j] - m - lse;
    }
}

// ---------------- launch ----------------
extern "C" void kernel_launch(void* const* d_in, const int* in_sizes, int n_in,
                              void* d_out, int out_size) {
    const float* x   = (const float*)d_in[0];
    const float* pos = (const float*)d_in[1];
    const int*   ei  = (const int*)d_in[2];
    const float* W1  = (const float*)d_in[4];
    const float* g1  = (const float*)d_in[5];
    const float* b1  = (const float*)d_in[6];
    const float* Wp1 = (const float*)d_in[7];
    const float* bp1 = (const float*)d_in[8];
    const float* Wp2 = (const float*)d_in[9];
    const float* bp2 = (const float*)d_in[10];
    const float* Wg1 = (const float*)d_in[11];
    const float* bg1 = (const float*)d_in[12];
    const float* Wg2 = (const float*)d_in[13];
    const float* bg2 = (const float*)d_in[14];
    const float* W2  = (const float*)d_in[15];
    const float* g2  = (const float*)d_in[16];
    const float* b2  = (const float*)d_in[17];
    const float* W3  = (const float*)d_in[18];
    const float* g3  = (const float*)d_in[19];
    const float* b3  = (const float*)d_in[20];
    const float* Wd  = (const float*)d_in[21];
    const float* bd  = (const float*)d_in[22];
    float* out = (float*)d_out;

    float *pGbuf, *pY3, *pSA2;
    __nv_bfloat16 *pH0h, *pH0l, *pA0h, *pA0l, *pH1h, *pH1l, *pA1h, *pA1l, *pH2h, *pH2l;
    __nv_bfloat16 *pWg1h, *pWg1l, *pWg2h, *pWg2l;
    cudaGetSymbolAddress((void**)&pGbuf, g_gbuf);
    cudaGetSymbolAddress((void**)&pY3,   g_y3);
    cudaGetSymbolAddress((void**)&pSA2,  g_sA2f);
    cudaGetSymbolAddress((void**)&pH0h,  g_h0h);
    cudaGetSymbolAddress((void**)&pH0l,  g_h0l);
    cudaGetSymbolAddress((void**)&pA0h,  g_agg0h);
    cudaGetSymbolAddress((void**)&pA0l,  g_agg0l);
    cudaGetSymbolAddress((void**)&pH1h,  g_h1h);
    cudaGetSymbolAddress((void**)&pH1l,  g_h1l);
    cudaGetSymbolAddress((void**)&pA1h,  g_agg1h);
    cudaGetSymbolAddress((void**)&pA1l,  g_agg1l);
    cudaGetSymbolAddress((void**)&pH2h,  g_h2h);
    cudaGetSymbolAddress((void**)&pH2l,  g_h2l);
    cudaGetSymbolAddress((void**)&pWg1h, g_Wg1th);
    cudaGetSymbolAddress((void**)&pWg1l, g_Wg1tl);
    cudaGetSymbolAddress((void**)&pWg2h, g_Wg2th);
    cudaGetSymbolAddress((void**)&pWg2l, g_Wg2tl);

    const int DSM = 2*STAGE_BYTES;
    cudaFuncSetAttribute(k_gemm_tc, cudaFuncAttributeMaxDynamicSharedMemorySize, DSM);
    cudaFuncSetAttribute(k_agg_tc, cudaFuncAttributeMaxDynamicSharedMemorySize, AGG_SMEM);
    cudaFuncSetAttribute(k_conv2_i8, cudaFuncAttributeMaxDynamicSharedMemorySize, 2*I8_STAGE);

    k_zero<<<128, 256>>>();
    k_deg<<<16, 256>>>(ei);
    k_adj<<<18, 256>>>(ei);
    k_asplit<<<128, 256>>>();
    k_wsplit<<<64, 256>>>(Wg1, pWg1h, pWg1l, 64, 256);
    k_wsplit<<<256, 256>>>(Wg2, pWg2h, pWg2l, 256, 256);
    k_wquant<<<128, 256>>>(W2);
    k_pe<<<512, 64>>>(pos, Wp1, bp1, Wp2, bp2);
    k_conv1<<<1024, 256>>>(x, W1);
    k_bn1pe<<<4096, 256>>>(g1, b1);

    // agg0 = A @ h0  (TC, split out)
    k_agg_tc<<<dim3(32, 8), 256, AGG_SMEM>>>(pH0h, pH0l, pA0h, pA0l, 8192);
    // gcn1: h1 = relu(agg0 @ Wg1^T + bg1)
    k_gemm_tc<<<dim3(2, 512), 256, DSM>>>(pA0h, pA0l, pWg1h, pWg1l, bg1,
                                          pH1h, pH1l, nullptr, 64, 256);
    // agg1 = A @ h1
    k_agg_tc<<<dim3(128, 8), 256, AGG_SMEM>>>(pH1h, pH1l, pA1h, pA1l, 32768);
    // gcn2: h2 = relu(agg1 @ Wg2^T + bg2) + per-node max
    k_gemm_tc<<<dim3(2, 512), 256, DSM>>>(pA1h, pA1l, pWg2h, pWg2l, bg2,
                                          pH2h, pH2l, pSA2, 256, 256);
    // quantize h2 to int8 slices
    k_h2quant<<<8192, 256>>>();
    // conv2 int8 implicit GEMM + fused BN2 stats
    k_conv2_i8<<<dim3(2, 488), 256, 2*I8_STAGE>>>();
    k_pool<<<dim3(4, 30, 8), 128>>>(g2, b2);
    // conv3 SIMT
    k_gemm<<<dim3(2, 4, 1), 256>>>(pGbuf, W3, pY3, 224, 128, 384, 28, 30, 128);
    k_bn3stats<<<1, 256>>>();
    k_tail<<<8, 128>>>(g3, b3, Wd, bd, out);
}

// round 6
// speedup vs baseline: 1.7162x; 1.7162x over previous
#include <cuda_runtime.h>
#include <cuda_bf16.h>
#include <math.h>
#include <stdint.h>

#define N_NODES 512
#define TT 128
#define NE 4096
#define C0 64
#define C1 128
#define C2 128
#define EMB 256
#define NG 8
#define EPSV 1e-5f

// ---------------- scratch (device globals; no allocs allowed) ----------------
__device__ float g_y1[N_NODES*TT*C0];            // conv1 raw out
__device__ float g_y2[N_NODES*122*C1];
__device__ float g_gbuf[NG*30*C1];
__device__ float g_y3[NG*28*C2];
__device__ float g_pe[N_NODES*C0];
__device__ float g_A[NG*64*64];
__device__ int   g_deg[N_NODES];
__device__ float g_s1[C0], g_sq1[C0];
__device__ float g_s2[C1], g_sq2[C1];
__device__ float g_mu3[C2], g_rs3[C2];

// bf16 split buffers
__device__ __nv_bfloat16 g_Ash[NG*64*64],        g_Asl[NG*64*64];
__device__ __nv_bfloat16 g_h0h[N_NODES*TT*C0],   g_h0l[N_NODES*TT*C0];
__device__ __nv_bfloat16 g_agg0h[N_NODES*TT*C0], g_agg0l[N_NODES*TT*C0];
__device__ __nv_bfloat16 g_h1h[N_NODES*TT*EMB],  g_h1l[N_NODES*TT*EMB];
__device__ __nv_bfloat16 g_agg1h[N_NODES*TT*EMB],g_agg1l[N_NODES*TT*EMB];
__device__ __nv_bfloat16 g_h2h[N_NODES*TT*EMB],  g_h2l[N_NODES*TT*EMB];
__device__ __nv_bfloat16 g_Wg1th[EMB*C0],  g_Wg1tl[EMB*C0];     // [256][64]
__device__ __nv_bfloat16 g_Wg2th[EMB*EMB], g_Wg2tl[EMB*EMB];    // [256][256]
__device__ __nv_bfloat16 g_W2th[C1*7*EMB], g_W2tl[C1*7*EMB];    // [128][1792]

// ---------------- helpers ----------------
__device__ __forceinline__ uint32_t smem_u32(const void* p) {
    uint32_t a;
    asm("{ .reg .u64 t; cvta.to.shared.u64 t, %1; cvt.u32.u64 %0, t; }" : "=r"(a) : "l"(p));
    return a;
}
#define CP16(dst, src) asm volatile("cp.async.cg.shared.global [%0], [%1], 16;" :: "r"(dst), "l"(src))
#define CP_COMMIT()    asm volatile("cp.async.commit_group;" ::: "memory")
#define CP_WAIT1()     asm volatile("cp.async.wait_group 1;" ::: "memory")
#define CP_WAIT0()     asm volatile("cp.async.wait_group 0;" ::: "memory")
#define LDSM_X4(r0, r1, r2, r3, addr) \
    asm volatile("ldmatrix.sync.aligned.m8n8.x4.shared.b16 {%0,%1,%2,%3}, [%4];" \
        : "=r"(r0), "=r"(r1), "=r"(r2), "=r"(r3) : "r"(addr))
#define LDSM_X4T(r0, r1, r2, r3, addr) \
    asm volatile("ldmatrix.sync.aligned.m8n8.x4.trans.shared.b16 {%0,%1,%2,%3}, [%4];" \
        : "=r"(r0), "=r"(r1), "=r"(r2), "=r"(r3) : "r"(addr))
#define MMA16816(d, a, b) \
    asm volatile("mma.sync.aligned.m16n8k16.row.col.f32.bf16.bf16.f32 " \
        "{%0,%1,%2,%3}, {%4,%5,%6,%7}, {%8,%9}, {%0,%1,%2,%3};" \
        : "+f"((d)[0]), "+f"((d)[1]), "+f"((d)[2]), "+f"((d)[3]) \
        : "r"((a)[0]), "r"((a)[1]), "r"((a)[2]), "r"((a)[3]), "r"((b)[0]), "r"((b)[1]))

__device__ __forceinline__ void split_store(__nv_bfloat16* H, __nv_bfloat16* L,
                                            long long idx, float v0, float v1) {
    __nv_bfloat16 h0 = __float2bfloat16(v0), h1 = __float2bfloat16(v1);
    __nv_bfloat162 hv; hv.x = h0; hv.y = h1;
    __nv_bfloat162 lv;
    lv.x = __float2bfloat16(v0 - __bfloat162float(h0));
    lv.y = __float2bfloat16(v1 - __bfloat162float(h1));
    *(__nv_bfloat162*)&H[idx] = hv;
    *(__nv_bfloat162*)&L[idx] = lv;
}

// ---------------- setup kernels ----------------
__global__ void k_zero() {
    int i = blockIdx.x*256 + threadIdx.x;
    if (i < NG*64*64) g_A[i] = 0.f;
    if (i < N_NODES)  g_deg[i] = 0;
    if (i < C0) { g_s1[i]=0.f; g_sq1[i]=0.f; }
    if (i < C1) { g_s2[i]=0.f; g_sq2[i]=0.f; }
    if (i < NG*30*C1) g_gbuf[i] = 0.f;
}

__global__ void k_deg(const int* __restrict__ ei) {
    int e = blockIdx.x*256 + threadIdx.x;
    if (e < NE) atomicAdd(&g_deg[ei[NE + e]], 1);
}

__global__ void k_adj(const int* __restrict__ ei) {
    int i = blockIdx.x*256 + threadIdx.x;
    if (i < NE) {
        int s = ei[i], d = ei[NE + i];
        float nr = rsqrtf((float)(g_deg[s]+1)) * rsqrtf((float)(g_deg[d]+1));
        int g = d >> 6;
        atomicAdd(&g_A[(g<<12) + ((d&63)<<6) + (s&63)], nr);
    } else if (i < NE + N_NODES) {
        int n = i - NE;
        float di = 1.f / (float)(g_deg[n]+1);
        atomicAdd(&g_A[((n>>6)<<12) + ((n&63)<<6) + (n&63)], di);
    }
}

__global__ void k_asplit() {
    int i = blockIdx.x*256 + threadIdx.x;
    float v = g_A[i];
    __nv_bfloat16 h = __float2bfloat16(v);
    g_Ash[i] = h;
    g_Asl[i] = __float2bfloat16(v - __bfloat162float(h));
}

// weight transpose + bf16 split: Wt[n][k] = W[k][n]
__global__ void k_wsplit(const float* __restrict__ W, __nv_bfloat16* __restrict__ hi,
                         __nv_bfloat16* __restrict__ lo, int K, int N) {
    int i = blockIdx.x*256 + threadIdx.x;
    if (i >= K*N) return;
    int n = i / K, k = i - n*K;
    float v = W[k*N + n];
    __nv_bfloat16 h = __float2bfloat16(v);
    hi[i] = h;
    lo[i] = __float2bfloat16(v - __bfloat162float(h));
}

__global__ void k_pe(const float* __restrict__ pos, const float* __restrict__ Wp1,
                     const float* __restrict__ bp1, const float* __restrict__ Wp2,
                     const float* __restrict__ bp2) {
    __shared__ float t1[64];
    int n = blockIdx.x, j = threadIdx.x;
    float p0 = pos[n*3], p1 = pos[n*3+1], p2 = pos[n*3+2];
    t1[j] = fmaxf(p0*Wp1[j] + p1*Wp1[64+j] + p2*Wp1[128+j] + bp1[j], 0.f);
    __syncthreads();
    float s = bp2[j];
    #pragma unroll 8
    for (int k = 0; k < 64; ++k) s += t1[k]*Wp2[k*64 + j];
    g_pe[n*64 + j] = s;
}

__global__ void k_conv1(const float* __restrict__ x, const float* __restrict__ W1) {
    __shared__ float sx[70];
    __shared__ float red[256];
    int b = blockIdx.x;
    int n = b >> 1;
    int t0 = (b & 1) * 64;
    int tid = threadIdx.x;
    if (tid < 70) {
        int t = t0 - 3 + tid;
        sx[tid] = (t >= 0 && t < TT) ? x[n*TT + t] : 0.f;
    }
    __syncthreads();
    int c = tid & 63, r0 = tid >> 6;
    float w[7];
    #pragma unroll
    for (int k = 0; k < 7; ++k) w[k] = W1[k*64 + c];
    float ls = 0.f, lq = 0.f;
    for (int rr = r0; rr < 64; rr += 4) {
        float y = 0.f;
        #pragma unroll
        for (int k = 0; k < 7; ++k) y += sx[rr + k] * w[k];
        g_y1[(b*64 + rr)*64 + c] = y;
        ls += y; lq += y*y;
    }
    red[tid] = ls; __syncthreads();
    if (tid < 64) atomicAdd(&g_s1[c], red[tid]+red[tid+64]+red[tid+128]+red[tid+192]);
    __syncthreads();
    red[tid] = lq; __syncthreads();
    if (tid < 64) atomicAdd(&g_sq1[c], red[tid]+red[tid+64]+red[tid+128]+red[tid+192]);
}

// BN1 apply + ReLU + add pe -> h0 bf16 split
__global__ void k_bn1pe(const float* __restrict__ g1w, const float* __restrict__ b1w) {
    int i4 = blockIdx.x*256 + threadIdx.x;
    int base = i4 * 4;
    int c0 = base & 63;
    int n = base >> 13;
    float4 v = *(float4*)&g_y1[base];
    float vv[4] = {v.x, v.y, v.z, v.w};
    #pragma unroll
    for (int j = 0; j < 4; ++j) {
        int c = c0 + j;
        float mu  = g_s1[c]  * (1.f/65536.f);
        float var = g_sq1[c] * (1.f/65536.f) - mu*mu;
        float a = g1w[c] * rsqrtf(var + EPSV);
        float bb = b1w[c] - mu*a;
        vv[j] = fmaxf(a*vv[j] + bb, 0.f) + g_pe[n*64 + c];
    }
    split_store(g_h0h, g_h0l, base,   vv[0], vv[1]);
    split_store(g_h0h, g_h0l, base+2, vv[2], vv[3]);
}

// ---------------- fp32 SIMT GEMM (conv3 only) ----------------
__global__ void k_gemm(const float* __restrict__ Aall, const float* __restrict__ Ball,
                       float* __restrict__ Call,
                       int M, int N, int K, int Tout, int Tin, int rowC)
{
    const float* A = Aall;
    const float* B = Ball;

    __shared__ __align__(16) float As[16][68];
    __shared__ __align__(16) float Bs[16][68];

    int tid = threadIdx.x;
    int tx = tid & 15, ty = tid >> 4;
    int m0 = blockIdx.y * 64;
    int n0 = blockIdx.x * 64;

    int abase[4]; bool aok[4];
    #pragma unroll
    for (int p = 0; p < 4; ++p) {
        int row = m0 + p*16 + (tid >> 4);
        aok[p] = (row < M);
        abase[p] = aok[p] ? ((row / Tout) * Tin + (row % Tout)) * rowC : 0;
    }
    int akk = tid & 15;

    float acc[4][4] = {};

    for (int k0 = 0; k0 < K; k0 += 16) {
        #pragma unroll
        for (int p = 0; p < 4; ++p) {
            float v = aok[p] ? A[abase[p] + k0 + akk] : 0.f;
            As[akk][p*16 + (tid >> 4)] = v;
        }
        #pragma unroll
        for (int p = 0; p < 4; ++p) {
            int kk = p*4 + (tid >> 6);
            Bs[kk][tid & 63] = B[(k0 + kk) * N + n0 + (tid & 63)];
        }
        __syncthreads();
        #pragma unroll
        for (int kk = 0; kk < 16; ++kk) {
            float4 av = *(const float4*)&As[kk][ty*4];
            float4 bv = *(const float4*)&Bs[kk][tx*4];
            float a_[4] = {av.x, av.y, av.z, av.w};
            float b_[4] = {bv.x, bv.y, bv.z, bv.w};
            #pragma unroll
            for (int i = 0; i < 4; ++i)
                #pragma unroll
                for (int j = 0; j < 4; ++j)
                    acc[i][j] += a_[i] * b_[j];
        }
        __syncthreads();
    }

    #pragma unroll
    for (int i = 0; i < 4; ++i) {
        int row = m0 + ty*4 + i;
        if (row >= M) continue;
        #pragma unroll
        for (int j = 0; j < 4; ++j) {
            int col = n0 + tx*4 + j;
            Call[(long long)row * N + col] = acc[i][j];
        }
    }
}

// ---------------- TC aggregation: O = A(64x64) @ H(64xF) per graph -----------
#define ASTR 72
#define HSTR 264
#define AGG_SMEM (2*64*ASTR*2 + 2*64*HSTR*2)   // 86016

__global__ void __launch_bounds__(256, 2)
k_agg_tc(const __nv_bfloat16* __restrict__ Hh, const __nv_bfloat16* __restrict__ Hl,
         __nv_bfloat16* __restrict__ Oh, __nv_bfloat16* __restrict__ Ol, int F)
{
    extern __shared__ char dsm[];
    uint32_t sAh = smem_u32(dsm);
    uint32_t sAl = sAh + 64*ASTR*2;
    uint32_t sHh = sAl + 64*ASTR*2;
    uint32_t sHl = sHh + 64*HSTR*2;

    int g = blockIdx.y;
    int n0 = blockIdx.x * 256;
    int tid = threadIdx.x, lane = tid & 31, wid = tid >> 5;

    const char* Agh = (const char*)(g_Ash + g*4096);
    const char* Agl = (const char*)(g_Asl + g*4096);
    #pragma unroll
    for (int it = 0; it < 2; ++it) {
        int sid = it*256 + tid;
        int row = sid >> 3, seg = (sid & 7) * 8;
        CP16(sAh + (row*ASTR + seg)*2, Agh + (row*64 + seg)*2);
        CP16(sAl + (row*ASTR + seg)*2, Agl + (row*64 + seg)*2);
    }
    long long hbase = (long long)(g*64) * F + n0;
    #pragma unroll
    for (int it = 0; it < 8; ++it) {
        int sid = it*256 + tid;
        int row = sid >> 5, seg = (sid & 31) * 8;
        long long go = (hbase + (long long)row*F + seg) * 2;
        CP16(sHh + (row*HSTR + seg)*2, (const char*)Hh + go);
        CP16(sHl + (row*HSTR + seg)*2, (const char*)Hl + go);
    }
    CP_COMMIT();
    CP_WAIT0();
    __syncthreads();

    float acc[4][4][4] = {};
    int nw = wid * 32;
    uint32_t arow = lane & 15, ahi = (lane >> 4) * 8;

    #pragma unroll
    for (int kk = 0; kk < 4; ++kk) {
        uint32_t ah[4][4], al[4][4];
        uint32_t acol = kk*16 + ahi;
        #pragma unroll
        for (int i = 0; i < 4; ++i) {
            LDSM_X4(ah[i][0], ah[i][1], ah[i][2], ah[i][3],
                    sAh + ((i*16 + arow)*ASTR + acol)*2);
            LDSM_X4(al[i][0], al[i][1], al[i][2], al[i][3],
                    sAl + ((i*16 + arow)*ASTR + acol)*2);
        }
        uint32_t brow = kk*16 + (lane & 15);
        #pragma unroll
        for (int jp = 0; jp < 2; ++jp) {
            uint32_t bh2[2][2], bl2[2][2];
            uint32_t bcol = nw + jp*16 + ahi;
            uint32_t t0, t1, t2, t3;
            LDSM_X4T(t0, t1, t2, t3, sHh + (brow*HSTR + bcol)*2);
            bh2[0][0] = t0; bh2[0][1] = t1; bh2[1][0] = t2; bh2[1][1] = t3;
            LDSM_X4T(t0, t1, t2, t3, sHl + (brow*HSTR + bcol)*2);
            bl2[0][0] = t0; bl2[0][1] = t1; bl2[1][0] = t2; bl2[1][1] = t3;
            #pragma unroll
            for (int i = 0; i < 4; ++i)
                #pragma unroll
                for (int j2 = 0; j2 < 2; ++j2) {
                    MMA16816(acc[i][jp*2+j2], ah[i], bh2[j2]);
                    MMA16816(acc[i][jp*2+j2], ah[i], bl2[j2]);
                    MMA16816(acc[i][jp*2+j2], al[i], bh2[j2]);
                }
        }
    }

    int rb = lane >> 2;
    int cb = n0 + nw + (lane & 3)*2;
    #pragma unroll
    for (int i = 0; i < 4; ++i)
        #pragma unroll
        for (int j = 0; j < 4; ++j)
            #pragma unroll
            for (int half = 0; half < 2; ++half) {
                int row = i*16 + rb + half*8;
                long long idx = (long long)(g*64 + row) * F + cb + j*8;
                split_store(Oh, Ol, idx, acc[i][j][half*2], acc[i][j][half*2+1]);
            }
}

// ---------------- bf16-split tensor-core GEMM via mma.sync --------------------
#define KC 32
#define LDS_STRIDE 40
#define ARR_BYTES (128*LDS_STRIDE*2)
#define STAGE_BYTES (4*ARR_BYTES)

__global__ void __launch_bounds__(256, 2)
k_gemm_tc(const __nv_bfloat16* __restrict__ Ah, const __nv_bfloat16* __restrict__ Al,
          const __nv_bfloat16* __restrict__ Bh, const __nv_bfloat16* __restrict__ Bl,
          const float* __restrict__ bias,
          float* __restrict__ Cf, __nv_bfloat16* __restrict__ Chi, __nv_bfloat16* __restrict__ Clo,
          int K, int Tout, int Tin, int rowC, int ldc, int mode)
{
    extern __shared__ char dsm[];
    uint32_t sbase = smem_u32(dsm);
    int tid = threadIdx.x, lane = tid & 31, wid = tid >> 5;
    int m0 = blockIdx.y * 128, n0 = blockIdx.x * 128;

    long long gA[2], gB[2];
    uint32_t so[2];
    #pragma unroll
    for (int p = 0; p < 2; ++p) {
        int row = p*64 + (tid >> 2);
        int seg = tid & 3;
        int rg = m0 + row;
        gA[p] = (long long)((rg / Tout) * Tin + (rg % Tout)) * rowC + seg*8;
        gB[p] = (long long)(n0 + row) * K + seg*8;
        so[p] = (uint32_t)(row*LDS_STRIDE + seg*8) * 2;
    }

    int wm = wid & 1, wn = wid >> 1;
    uint32_t aoff = (uint32_t)((wm*64 + (lane & 15))*LDS_STRIDE + (lane >> 4)*8) * 2;
    uint32_t boff = (uint32_t)((wn*32 + ((lane >> 4) & 1)*8 + (lane & 7))*LDS_STRIDE
                               + ((lane >> 3) & 1)*8) * 2;

    float acc[4][4][4] = {};

    int nc = K >> 5;
    {
        uint32_t st = sbase;
        #pragma unroll
        for (int p = 0; p < 2; ++p) {
            CP16(st +              so[p], (const char*)Ah + gA[p]*2);
            CP16(st + ARR_BYTES  + so[p], (const char*)Al + gA[p]*2);
            CP16(st + 2*ARR_BYTES+ so[p], (const char*)Bh + gB[p]*2);
            CP16(st + 3*ARR_BYTES+ so[p], (const char*)Bl + gB[p]*2);
        }
    }
    CP_COMMIT();

    for (int c = 0; c < nc; ++c) {
        if (c + 1 < nc) {
            uint32_t st = sbase + ((c+1) & 1)*STAGE_BYTES;
            long long k0 = (long long)(c+1)*KC;
            #pragma unroll
            for (int p = 0; p < 2; ++p) {
                CP16(st +              so[p], (const char*)Ah + (gA[p]+k0)*2);
                CP16(st + ARR_BYTES  + so[p], (const char*)Al + (gA[p]+k0)*2);
                CP16(st + 2*ARR_BYTES+ so[p], (const char*)Bh + (gB[p]+k0)*2);
                CP16(st + 3*ARR_BYTES+ so[p], (const char*)Bl + (gB[p]+k0)*2);
            }
        }
        CP_COMMIT();
        CP_WAIT1();
        __syncthreads();

        uint32_t st = sbase + (c & 1)*STAGE_BYTES;
        uint32_t aAh = st + aoff,               aAl = st + ARR_BYTES   + aoff;
        uint32_t aBh = st + 2*ARR_BYTES + boff, aBl = st + 3*ARR_BYTES + boff;

        #pragma unroll
        for (int k16 = 0; k16 < 2; ++k16) {
            uint32_t kb = k16 * 32;
            uint32_t ah[4][4], al[4][4];
            #pragma unroll
            for (int i = 0; i < 4; ++i) {
                LDSM_X4(ah[i][0], ah[i][1], ah[i][2], ah[i][3], aAh + kb + i*(16*LDS_STRIDE*2));
                LDSM_X4(al[i][0], al[i][1], al[i][2], al[i][3], aAl + kb + i*(16*LDS_STRIDE*2));
            }
            #pragma unroll
            for (int jj = 0; jj < 2; ++jj) {
                uint32_t bh2[2][2], bl2[2][2];
                uint32_t t0, t1, t2, t3;
                LDSM_X4(t0, t1, t2, t3, aBh + kb + jj*(16*LDS_STRIDE*2));
                bh2[0][0] = t0; bh2[0][1] = t1; bh2[1][0] = t2; bh2[1][1] = t3;
                LDSM_X4(t0, t1, t2, t3, aBl + kb + jj*(16*LDS_STRIDE*2));
                bl2[0][0] = t0; bl2[0][1] = t1; bl2[1][0] = t2; bl2[1][1] = t3;
                #pragma unroll
                for (int i = 0; i < 4; ++i)
                    #pragma unroll
                    for (int j2 = 0; j2 < 2; ++j2) {
                        MMA16816(acc[i][jj*2+j2], ah[i], bh2[j2]);
                        MMA16816(acc[i][jj*2+j2], ah[i], bl2[j2]);
                        MMA16816(acc[i][jj*2+j2], al[i], bh2[j2]);
                    }
            }
        }
        __syncthreads();
    }

    int rbase = m0 + wm*64 + (lane >> 2);
    int cbase = n0 + wn*32 + (lane & 3)*2;
    #pragma unroll
    for (int i = 0; i < 4; ++i) {
        #pragma unroll
        for (int j = 0; j < 4; ++j) {
            int gc = cbase + j*8;
            #pragma unroll
            for (int half = 0; half < 2; ++half) {
                long long gr = rbase + i*16 + half*8;
                float v0 = acc[i][j][half*2], v1 = acc[i][j][half*2 + 1];
                if (mode >= 1) {
                    v0 = fmaxf(v0 + bias[gc], 0.f);
                    v1 = fmaxf(v1 + bias[gc+1], 0.f);
                }
                long long idx = gr * ldc + gc;
                if (mode == 2) {
                    split_store(Chi, Clo, idx, v0, v1);
                } else {
                    *(float2*)&Cf[idx] = make_float2(v0, v1);
                }
            }
        }
    }
}

// ---------------- BN2 / pool / BN3 / tail ----------------
__global__ void k_bn2stats() {
    __shared__ float red[256];
    int tid = threadIdx.x;
    int c = tid & 127, r0 = tid >> 7;
    int row0 = blockIdx.x * 128;
    float ls = 0.f, lq = 0.f;
    for (int r = r0; r < 128; r += 2) {
        float v = g_y2[(row0 + r)*128 + c];
        ls += v; lq += v*v;
    }
    red[tid] = ls; __syncthreads();
    if (tid < 128) atomicAdd(&g_s2[c], red[tid] + red[tid+128]);
    __syncthreads();
    red[tid] = lq; __syncthreads();
    if (tid < 128) atomicAdd(&g_sq2[c], red[tid] + red[tid+128]);
}

__global__ void k_pool(const float* __restrict__ g2w, const float* __restrict__ b2w) {
    int c = threadIdx.x;
    int chunk = blockIdx.x;
    int tp = blockIdx.y;
    int g = blockIdx.z;
    float mu  = g_s2[c]  * (1.f/62464.f);
    float var = g_sq2[c] * (1.f/62464.f) - mu*mu;
    float a = g2w[c] * rsqrtf(var + EPSV);
    float bb = b2w[c] - mu*a;
    float acc = 0.f;
    for (int nl = 0; nl < 16; ++nl) {
        int n = g*64 + chunk*16 + nl;
        const float* p = &g_y2[(n*122 + tp*4)*128 + c];
        float s4 = p[0] + p[128] + p[256] + p[384];
        acc += fmaxf(a * (s4 * 0.25f) + bb, 0.f);
    }
    atomicAdd(&g_gbuf[(g*30 + tp)*128 + c], acc * (1.f/64.f));
}

__global__ void k_bn3stats() {
    __shared__ float red[256];
    int tid = threadIdx.x;
    int c = tid & 127, r0 = tid >> 7;
    float ls = 0.f, lq = 0.f;
    for (int r = r0; r < 224; r += 2) { float v = g_y3[r*128 + c]; ls += v; lq += v*v; }
    red[tid] = ls; __syncthreads();
    float ssum = 0.f;
    if (tid < 128) ssum = red[tid] + red[tid+128];
    __syncthreads();
    red[tid] = lq; __syncthreads();
    if (tid < 128) {
        float q = red[tid] + red[tid+128];
        float mu = ssum * (1.f/224.f);
        float var = q * (1.f/224.f) - mu*mu;
        g_mu3[tid] = mu;
        g_rs3[tid] = rsqrtf(var + EPSV);
    }
}

__global__ void k_tail(const float* __restrict__ g3w, const float* __restrict__ b3w,
                       const float* __restrict__ Wd, const float* __restrict__ bd,
                       float* __restrict__ out) {
    __shared__ float gg[896];
    __shared__ float slog[4];
    int b = blockIdx.x, tid = threadIdx.x;
    int c = tid;
    float a = g3w[c] * g_rs3[c];
    float bb = b3w[c] - g_mu3[c]*a;
    #pragma unroll
    for (int tp = 0; tp < 7; ++tp) {
        const float* p = &g_y3[(b*28 + tp*4)*128 + c];
        float s4 = (p[0] + p[128] + p[256] + p[384]) * 0.25f;
        gg[tp*128 + c] = fmaxf(a*s4 + bb, 0.f);
    }
    __syncthreads();
    int w = tid >> 5, lane = tid & 31;
    float s = 0.f;
    for (int i = lane; i < 896; i += 32) s += gg[i] * Wd[i*4 + w];
    #pragma unroll
    for (int off = 16; off; off >>= 1) s += __shfl_xor_sync(0xffffffffu, s, off);
    if (lane == 0) slog[w] = s + bd[w];
    __syncthreads();
    if (tid == 0) {
        float m = fmaxf(fmaxf(slog[0], slog[1]), fmaxf(slog[2], slog[3]));
        float se = expf(slog[0]-m)+expf(slog[1]-m)+expf(slog[2]-m)+expf(slog[3]-m);
        float lse = logf(se);
        #pragma unroll
        for (int j = 0; j < 4; ++j) out[b*4 + j] = slog[j] - m - lse;
    }
}

// ---------------- launch ----------------
extern "C" void kernel_launch(void* const* d_in, const int* in_sizes, int n_in,
                              void* d_out, int out_size) {
    const float* x   = (const float*)d_in[0];
    const float* pos = (const float*)d_in[1];
    const int*   ei  = (const int*)d_in[2];
    const float* W1  = (const float*)d_in[4];
    const float* g1  = (const float*)d_in[5];
    const float* b1  = (const float*)d_in[6];
    const float* Wp1 = (const float*)d_in[7];
    const float* bp1 = (const float*)d_in[8];
    const float* Wp2 = (const float*)d_in[9];
    const float* bp2 = (const float*)d_in[10];
    const float* Wg1 = (const float*)d_in[11];
    const float* bg1 = (const float*)d_in[12];
    const float* Wg2 = (const float*)d_in[13];
    const float* bg2 = (const float*)d_in[14];
    const float* W2  = (const float*)d_in[15];
    const float* g2  = (const float*)d_in[16];
    const float* b2  = (const float*)d_in[17];
    const float* W3  = (const float*)d_in[18];
    const float* g3  = (const float*)d_in[19];
    const float* b3  = (const float*)d_in[20];
    const float* Wd  = (const float*)d_in[21];
    const float* bd  = (const float*)d_in[22];
    float* out = (float*)d_out;

    float *pY2, *pGbuf, *pY3;
    __nv_bfloat16 *pH0h, *pH0l, *pA0h, *pA0l, *pH1h, *pH1l, *pA1h, *pA1l, *pH2h, *pH2l;
    __nv_bfloat16 *pWg1h, *pWg1l, *pWg2h, *pWg2l, *pW2h, *pW2l;
    cudaGetSymbolAddress((void**)&pY2,   g_y2);
    cudaGetSymbolAddress((void**)&pGbuf, g_gbuf);
    cudaGetSymbolAddress((void**)&pY3,   g_y3);
    cudaGetSymbolAddress((void**)&pH0h,  g_h0h);
    cudaGetSymbolAddress((void**)&pH0l,  g_h0l);
    cudaGetSymbolAddress((void**)&pA0h,  g_agg0h);
    cudaGetSymbolAddress((void**)&pA0l,  g_agg0l);
    cudaGetSymbolAddress((void**)&pH1h,  g_h1h);
    cudaGetSymbolAddress((void**)&pH1l,  g_h1l);
    cudaGetSymbolAddress((void**)&pA1h,  g_agg1h);
    cudaGetSymbolAddress((void**)&pA1l,  g_agg1l);
    cudaGetSymbolAddress((void**)&pH2h,  g_h2h);
    cudaGetSymbolAddress((void**)&pH2l,  g_h2l);
    cudaGetSymbolAddress((void**)&pWg1h, g_Wg1th);
    cudaGetSymbolAddress((void**)&pWg1l, g_Wg1tl);
    cudaGetSymbolAddress((void**)&pWg2h, g_Wg2th);
    cudaGetSymbolAddress((void**)&pWg2l, g_Wg2tl);
    cudaGetSymbolAddress((void**)&pW2h,  g_W2th);
    cudaGetSymbolAddress((void**)&pW2l,  g_W2tl);

    const int DSM = 2*STAGE_BYTES;   // 81920
    cudaFuncSetAttribute(k_gemm_tc, cudaFuncAttributeMaxDynamicSharedMemorySize, DSM);
    cudaFuncSetAttribute(k_agg_tc, cudaFuncAttributeMaxDynamicSharedMemorySize, AGG_SMEM);

    k_zero<<<128, 256>>>();
    k_deg<<<16, 256>>>(ei);
    k_adj<<<18, 256>>>(ei);
    k_asplit<<<128, 256>>>();
    k_wsplit<<<64, 256>>>(Wg1, pWg1h, pWg1l, 64, 256);
    k_wsplit<<<256, 256>>>(Wg2, pWg2h, pWg2l, 256, 256);
    k_wsplit<<<896, 256>>>(W2, pW2h, pW2l, 1792, 128);
    k_pe<<<512, 64>>>(pos, Wp1, bp1, Wp2, bp2);
    k_conv1<<<1024, 256>>>(x, W1);
    k_bn1pe<<<4096, 256>>>(g1, b1);

    // agg0 = A @ h0  (TC, split out), F = T*C0 = 8192
    k_agg_tc<<<dim3(32, 8), 256, AGG_SMEM>>>(pH0h, pH0l, pA0h, pA0l, 8192);
    // gcn1: h1 = relu(agg0 @ Wg1^T + bg1)  (TC, split out)
    k_gemm_tc<<<dim3(2, 512), 256, DSM>>>(pA0h, pA0l, pWg1h, pWg1l, bg1,
                                          nullptr, pH1h, pH1l,
                                          64, 65536, 65536, 64, 256, 2);
    // agg1 = A @ h1  (TC, split out), F = T*EMB = 32768
    k_agg_tc<<<dim3(128, 8), 256, AGG_SMEM>>>(pH1h, pH1l, pA1h, pA1l, 32768);
    // gcn2: h2 = relu(agg1 @ Wg2^T + bg2)  (TC, split out)
    k_gemm_tc<<<dim3(2, 512), 256, DSM>>>(pA1h, pA1l, pWg2h, pWg2l, bg2,
                                          nullptr, pH2h, pH2l,
                                          256, 65536, 65536, 256, 256, 2);
    // conv2 (k=7 VALID, 256->128) implicit GEMM (TC, fp32 out)
    k_gemm_tc<<<dim3(1, 488), 256, DSM>>>(pH2h, pH2l, pW2h, pW2l, nullptr,
                                          pY2, nullptr, nullptr,
                                          1792, 122, 128, 256, 128, 0);
    k_bn2stats<<<488, 256>>>();
    k_pool<<<dim3(4, 30, 8), 128>>>(g2, b2);
    // conv3 (k=3 VALID, 128->128) SIMT
    k_gemm<<<dim3(2, 4, 1), 256>>>(pGbuf, W3, pY3, 224, 128, 384, 28, 30, 128);
    k_bn3stats<<<1, 256>>>();
    k_tail<<<8, 128>>>(g3, b3, Wd, bd, out);
}

// round 7
// speedup vs baseline: 1.7270x; 1.0063x over previous
#include <cuda_runtime.h>
#include <cuda_bf16.h>
#include <math.h>
#include <stdint.h>

#define N_NODES 512
#define TT 128
#define NE 4096
#define C0 64
#define C1 128
#define C2 128
#define EMB 256
#define NG 8
#define EPSV 1e-5f

// ---------------- scratch (device globals; no allocs allowed) ----------------
__device__ float g_y2[N_NODES*122*C1];
__device__ float g_gbuf[NG*30*C1];
__device__ float g_y3[NG*28*C2];
__device__ float g_pe[N_NODES*C0];
__device__ float g_A[NG*64*64];
__device__ int   g_deg[N_NODES];
__device__ float g_s1[C0], g_sq1[C0];
__device__ float g_s2[C1], g_sq2[C1];
__device__ float g_mu3[C2], g_rs3[C2];

// bf16 split buffers
__device__ __nv_bfloat16 g_Ash[NG*64*64],        g_Asl[NG*64*64];
__device__ __nv_bfloat16 g_h0h[N_NODES*TT*C0],   g_h0l[N_NODES*TT*C0];
__device__ __nv_bfloat16 g_agg0h[N_NODES*TT*C0], g_agg0l[N_NODES*TT*C0];
__device__ __nv_bfloat16 g_h1h[N_NODES*TT*EMB],  g_h1l[N_NODES*TT*EMB];
__device__ __nv_bfloat16 g_agg1h[N_NODES*TT*EMB],g_agg1l[N_NODES*TT*EMB];
__device__ __nv_bfloat16 g_h2h[N_NODES*TT*EMB],  g_h2l[N_NODES*TT*EMB];
__device__ __nv_bfloat16 g_Wg1th[EMB*C0],  g_Wg1tl[EMB*C0];     // [256][64]
__device__ __nv_bfloat16 g_Wg2th[EMB*EMB], g_Wg2tl[EMB*EMB];    // [256][256]
__device__ __nv_bfloat16 g_W2th[C1*7*EMB], g_W2tl[C1*7*EMB];    // [128][1792]

// ---------------- helpers ----------------
__device__ __forceinline__ uint32_t smem_u32(const void* p) {
    uint32_t a;
    asm("{ .reg .u64 t; cvta.to.shared.u64 t, %1; cvt.u32.u64 %0, t; }" : "=r"(a) : "l"(p));
    return a;
}
#define CP16(dst, src) asm volatile("cp.async.cg.shared.global [%0], [%1], 16;" :: "r"(dst), "l"(src))
#define CP_COMMIT()    asm volatile("cp.async.commit_group;" ::: "memory")
#define CP_WAIT1()     asm volatile("cp.async.wait_group 1;" ::: "memory")
#define CP_WAIT0()     asm volatile("cp.async.wait_group 0;" ::: "memory")
#define LDSM_X4(r0, r1, r2, r3, addr) \
    asm volatile("ldmatrix.sync.aligned.m8n8.x4.shared.b16 {%0,%1,%2,%3}, [%4];" \
        : "=r"(r0), "=r"(r1), "=r"(r2), "=r"(r3) : "r"(addr))
#define LDSM_X4T(r0, r1, r2, r3, addr) \
    asm volatile("ldmatrix.sync.aligned.m8n8.x4.trans.shared.b16 {%0,%1,%2,%3}, [%4];" \
        : "=r"(r0), "=r"(r1), "=r"(r2), "=r"(r3) : "r"(addr))
#define MMA16816(d, a, b) \
    asm volatile("mma.sync.aligned.m16n8k16.row.col.f32.bf16.bf16.f32 " \
        "{%0,%1,%2,%3}, {%4,%5,%6,%7}, {%8,%9}, {%0,%1,%2,%3};" \
        : "+f"((d)[0]), "+f"((d)[1]), "+f"((d)[2]), "+f"((d)[3]) \
        : "r"((a)[0]), "r"((a)[1]), "r"((a)[2]), "r"((a)[3]), "r"((b)[0]), "r"((b)[1]))

__device__ __forceinline__ void split_store(__nv_bfloat16* H, __nv_bfloat16* L,
                                            long long idx, float v0, float v1) {
    __nv_bfloat16 h0 = __float2bfloat16(v0), h1 = __float2bfloat16(v1);
    __nv_bfloat162 hv; hv.x = h0; hv.y = h1;
    __nv_bfloat162 lv;
    lv.x = __float2bfloat16(v0 - __bfloat162float(h0));
    lv.y = __float2bfloat16(v1 - __bfloat162float(h1));
    *(__nv_bfloat162*)&H[idx] = hv;
    *(__nv_bfloat162*)&L[idx] = lv;
}

__device__ __forceinline__ void split1(float v, __nv_bfloat16* H, __nv_bfloat16* L, int idx) {
    __nv_bfloat16 h = __float2bfloat16(v);
    H[idx] = h;
    L[idx] = __float2bfloat16(v - __bfloat162float(h));
}

// ---------------- setup kernels ----------------
__global__ void k_zero() {
    int i = blockIdx.x*256 + threadIdx.x;
    if (i < NG*64*64) g_A[i] = 0.f;
    if (i < N_NODES)  g_deg[i] = 0;
    if (i < C0) { g_s1[i]=0.f; g_sq1[i]=0.f; }
    if (i < C1) { g_s2[i]=0.f; g_sq2[i]=0.f; }
    if (i < NG*30*C1) g_gbuf[i] = 0.f;
}

__global__ void k_deg(const int* __restrict__ ei) {
    int e = blockIdx.x*256 + threadIdx.x;
    if (e < NE) atomicAdd(&g_deg[ei[NE + e]], 1);
}

__global__ void k_adj(const int* __restrict__ ei) {
    int i = blockIdx.x*256 + threadIdx.x;
    if (i < NE) {
        int s = ei[i], d = ei[NE + i];
        float nr = rsqrtf((float)(g_deg[s]+1)) * rsqrtf((float)(g_deg[d]+1));
        int g = d >> 6;
        atomicAdd(&g_A[(g<<12) + ((d&63)<<6) + (s&63)], nr);
    } else if (i < NE + N_NODES) {
        int n = i - NE;
        float di = 1.f / (float)(g_deg[n]+1);
        atomicAdd(&g_A[((n>>6)<<12) + ((n&63)<<6) + (n&63)], di);
    }
}

// fused weight/adjacency prep: Wg1t, Wg2t, W2t transposed splits + A split
__global__ void k_wprep(const float* __restrict__ Wg1, const float* __restrict__ Wg2,
                        const float* __restrict__ W2) {
    int i = blockIdx.x*256 + threadIdx.x;
    if (i < 16384) {
        int n = i >> 6, k = i & 63;
        split1(Wg1[k*256 + n], g_Wg1th, g_Wg1tl, i);
    } else if (i < 81920) {
        int j = i - 16384;
        int n = j >> 8, k = j & 255;
        split1(Wg2[k*256 + n], g_Wg2th, g_Wg2tl, j);
    } else if (i < 311296) {
        int j = i - 81920;
        int n = j / 1792, k = j - n*1792;
        split1(W2[k*128 + n], g_W2th, g_W2tl, j);
    } else if (i < 344064) {
        int j = i - 311296;
        split1(g_A[j], g_Ash, g_Asl, j);
    }
}

__global__ void k_pe(const float* __restrict__ pos, const float* __restrict__ Wp1,
                     const float* __restrict__ bp1, const float* __restrict__ Wp2,
                     const float* __restrict__ bp2) {
    __shared__ float t1[64];
    int n = blockIdx.x, j = threadIdx.x;
    float p0 = pos[n*3], p1 = pos[n*3+1], p2 = pos[n*3+2];
    t1[j] = fmaxf(p0*Wp1[j] + p1*Wp1[64+j] + p2*Wp1[128+j] + bp1[j], 0.f);
    __syncthreads();
    float s = bp2[j];
    #pragma unroll 8
    for (int k = 0; k < 64; ++k) s += t1[k]*Wp2[k*64 + j];
    g_pe[n*64 + j] = s;
}

// conv1 BN statistics only (y1 never materialized; recomputed in k_bn1pe)
__global__ void k_conv1stats(const float* __restrict__ x, const float* __restrict__ W1) {
    __shared__ float sx[70];
    __shared__ float red[256];
    int b = blockIdx.x;
    int n = b >> 1;
    int t0 = (b & 1) * 64;
    int tid = threadIdx.x;
    if (tid < 70) {
        int t = t0 - 3 + tid;
        sx[tid] = (t >= 0 && t < TT) ? x[n*TT + t] : 0.f;
    }
    __syncthreads();
    int c = tid & 63, r0 = tid >> 6;
    float w[7];
    #pragma unroll
    for (int k = 0; k < 7; ++k) w[k] = W1[k*64 + c];
    float ls = 0.f, lq = 0.f;
    for (int rr = r0; rr < 64; rr += 4) {
        float y = 0.f;
        #pragma unroll
        for (int k = 0; k < 7; ++k) y += sx[rr + k] * w[k];
        ls += y; lq += y*y;
    }
    red[tid] = ls; __syncthreads();
    if (tid < 64) atomicAdd(&g_s1[c], red[tid]+red[tid+64]+red[tid+128]+red[tid+192]);
    __syncthreads();
    red[tid] = lq; __syncthreads();
    if (tid < 64) atomicAdd(&g_sq1[c], red[tid]+red[tid+64]+red[tid+128]+red[tid+192]);
}

// recompute conv1 + BN1 apply + ReLU + add pe -> h0 bf16 split
__global__ void k_bn1pe(const float* __restrict__ x, const float* __restrict__ W1,
                        const float* __restrict__ g1w, const float* __restrict__ b1w) {
    __shared__ float sx[70];
    int b = blockIdx.x;
    int n = b >> 1;
    int t0 = (b & 1) * 64;
    int tid = threadIdx.x;
    if (tid < 70) {
        int t = t0 - 3 + tid;
        sx[tid] = (t >= 0 && t < TT) ? x[n*TT + t] : 0.f;
    }
    __syncthreads();
    int c0 = (tid & 31) * 2;
    int r0 = tid >> 5;
    float w0[7], w1[7];
    #pragma unroll
    for (int k = 0; k < 7; ++k) { w0[k] = W1[k*64 + c0]; w1[k] = W1[k*64 + c0 + 1]; }
    float mu0  = g_s1[c0]   * (1.f/65536.f);
    float var0 = g_sq1[c0]  * (1.f/65536.f) - mu0*mu0;
    float a0 = g1w[c0] * rsqrtf(var0 + EPSV);
    float bb0 = b1w[c0] - mu0*a0;
    float mu1  = g_s1[c0+1]  * (1.f/65536.f);
    float var1 = g_sq1[c0+1] * (1.f/65536.f) - mu1*mu1;
    float a1 = g1w[c0+1] * rsqrtf(var1 + EPSV);
    float bb1 = b1w[c0+1] - mu1*a1;
    float pe0 = g_pe[n*64 + c0], pe1 = g_pe[n*64 + c0 + 1];
    for (int r = r0; r < 64; r += 8) {
        float y0 = 0.f, y1 = 0.f;
        #pragma unroll
        for (int k = 0; k < 7; ++k) { y0 += sx[r+k]*w0[k]; y1 += sx[r+k]*w1[k]; }
        float v0 = fmaxf(a0*y0 + bb0, 0.f) + pe0;
        float v1 = fmaxf(a1*y1 + bb1, 0.f) + pe1;
        split_store(g_h0h, g_h0l, (long long)(b*64 + r)*64 + c0, v0, v1);
    }
}

// ---------------- fp32 SIMT GEMM (conv3 only) ----------------
__global__ void k_gemm(const float* __restrict__ Aall, const float* __restrict__ Ball,
                       float* __restrict__ Call,
                       int M, int N, int K, int Tout, int Tin, int rowC)
{
    const float* A = Aall;
    const float* B = Ball;

    __shared__ __align__(16) float As[16][68];
    __shared__ __align__(16) float Bs[16][68];

    int tid = threadIdx.x;
    int tx = tid & 15, ty = tid >> 4;
    int m0 = blockIdx.y * 64;
    int n0 = blockIdx.x * 64;

    int abase[4]; bool aok[4];
    #pragma unroll
    for (int p = 0; p < 4; ++p) {
        int row = m0 + p*16 + (tid >> 4);
        aok[p] = (row < M);
        abase[p] = aok[p] ? ((row / Tout) * Tin + (row % Tout)) * rowC : 0;
    }
    int akk = tid & 15;

    float acc[4][4] = {};

    for (int k0 = 0; k0 < K; k0 += 16) {
        #pragma unroll
        for (int p = 0; p < 4; ++p) {
            float v = aok[p] ? A[abase[p] + k0 + akk] : 0.f;
            As[akk][p*16 + (tid >> 4)] = v;
        }
        #pragma unroll
        for (int p = 0; p < 4; ++p) {
            int kk = p*4 + (tid >> 6);
            Bs[kk][tid & 63] = B[(k0 + kk) * N + n0 + (tid & 63)];
        }
        __syncthreads();
        #pragma unroll
        for (int kk = 0; kk < 16; ++kk) {
            float4 av = *(const float4*)&As[kk][ty*4];
            float4 bv = *(const float4*)&Bs[kk][tx*4];
            float a_[4] = {av.x, av.y, av.z, av.w};
            float b_[4] = {bv.x, bv.y, bv.z, bv.w};
            #pragma unroll
            for (int i = 0; i < 4; ++i)
                #pragma unroll
                for (int j = 0; j < 4; ++j)
                    acc[i][j] += a_[i] * b_[j];
        }
        __syncthreads();
    }

    #pragma unroll
    for (int i = 0; i < 4; ++i) {
        int row = m0 + ty*4 + i;
        if (row >= M) continue;
        #pragma unroll
        for (int j = 0; j < 4; ++j) {
            int col = n0 + tx*4 + j;
            Call[(long long)row * N + col] = acc[i][j];
        }
    }
}

// ---------------- TC aggregation: O = A(64x64) @ H(64xF) per graph -----------
#define ASTR 72
#define HSTR 264
#define AGG_SMEM (2*64*ASTR*2 + 2*64*HSTR*2)   // 86016

__global__ void __launch_bounds__(256, 2)
k_agg_tc(const __nv_bfloat16* __restrict__ Hh, const __nv_bfloat16* __restrict__ Hl,
         __nv_bfloat16* __restrict__ Oh, __nv_bfloat16* __restrict__ Ol, int F)
{
    extern __shared__ char dsm[];
    uint32_t sAh = smem_u32(dsm);
    uint32_t sAl = sAh + 64*ASTR*2;
    uint32_t sHh = sAl + 64*ASTR*2;
    uint32_t sHl = sHh + 64*HSTR*2;

    int g = blockIdx.y;
    int n0 = blockIdx.x * 256;
    int tid = threadIdx.x, lane = tid & 31, wid = tid >> 5;

    const char* Agh = (const char*)(g_Ash + g*4096);
    const char* Agl = (const char*)(g_Asl + g*4096);
    #pragma unroll
    for (int it = 0; it < 2; ++it) {
        int sid = it*256 + tid;
        int row = sid >> 3, seg = (sid & 7) * 8;
        CP16(sAh + (row*ASTR + seg)*2, Agh + (row*64 + seg)*2);
        CP16(sAl + (row*ASTR + seg)*2, Agl + (row*64 + seg)*2);
    }
    long long hbase = (long long)(g*64) * F + n0;
    #pragma unroll
    for (int it = 0; it < 8; ++it) {
        int sid = it*256 + tid;
        int row = sid >> 5, seg = (sid & 31) * 8;
        long long go = (hbase + (long long)row*F + seg) * 2;
        CP16(sHh + (row*HSTR + seg)*2, (const char*)Hh + go);
        CP16(sHl + (row*HSTR + seg)*2, (const char*)Hl + go);
    }
    CP_COMMIT();
    CP_WAIT0();
    __syncthreads();

    float acc[4][4][4] = {};
    int nw = wid * 32;
    uint32_t arow = lane & 15, ahi = (lane >> 4) * 8;

    #pragma unroll
    for (int kk = 0; kk < 4; ++kk) {
        uint32_t ah[4][4], al[4][4];
        uint32_t acol = kk*16 + ahi;
        #pragma unroll
        for (int i = 0; i < 4; ++i) {
            LDSM_X4(ah[i][0], ah[i][1], ah[i][2], ah[i][3],
                    sAh + ((i*16 + arow)*ASTR + acol)*2);
            LDSM_X4(al[i][0], al[i][1], al[i][2], al[i][3],
                    sAl + ((i*16 + arow)*ASTR + acol)*2);
        }
        uint32_t brow = kk*16 + (lane & 15);
        #pragma unroll
        for (int jp = 0; jp < 2; ++jp) {
            uint32_t bh2[2][2], bl2[2][2];
            uint32_t bcol = nw + jp*16 + ahi;
            uint32_t t0, t1, t2, t3;
            LDSM_X4T(t0, t1, t2, t3, sHh + (brow*HSTR + bcol)*2);
            bh2[0][0] = t0; bh2[0][1] = t1; bh2[1][0] = t2; bh2[1][1] = t3;
            LDSM_X4T(t0, t1, t2, t3, sHl + (brow*HSTR + bcol)*2);
            bl2[0][0] = t0; bl2[0][1] = t1; bl2[1][0] = t2; bl2[1][1] = t3;
            #pragma unroll
            for (int i = 0; i < 4; ++i)
                #pragma unroll
                for (int j2 = 0; j2 < 2; ++j2) {
                    MMA16816(acc[i][jp*2+j2], ah[i], bh2[j2]);
                    MMA16816(acc[i][jp*2+j2], ah[i], bl2[j2]);
                    MMA16816(acc[i][jp*2+j2], al[i], bh2[j2]);
                }
        }
    }

    int rb = lane >> 2;
    int cb = n0 + nw + (lane & 3)*2;
    #pragma unroll
    for (int i = 0; i < 4; ++i)
        #pragma unroll
        for (int j = 0; j < 4; ++j)
            #pragma unroll
            for (int half = 0; half < 2; ++half) {
                int row = i*16 + rb + half*8;
                long long idx = (long long)(g*64 + row) * F + cb + j*8;
                split_store(Oh, Ol, idx, acc[i][j][half*2], acc[i][j][half*2+1]);
            }
}

// ---------------- bf16-split tensor-core GEMM via mma.sync --------------------
// mode 0: fp32 store; 2: bias+relu -> bf16 split store; 3: fp32 store + BN2 stats
#define KC 32
#define LDS_STRIDE 40
#define ARR_BYTES (128*LDS_STRIDE*2)
#define STAGE_BYTES (4*ARR_BYTES)

__global__ void __launch_bounds__(256, 2)
k_gemm_tc(const __nv_bfloat16* __restrict__ Ah, const __nv_bfloat16* __restrict__ Al,
          const __nv_bfloat16* __restrict__ Bh, const __nv_bfloat16* __restrict__ Bl,
          const float* __restrict__ bias,
          float* __restrict__ Cf, __nv_bfloat16* __restrict__ Chi, __nv_bfloat16* __restrict__ Clo,
          int K, int Tout, int Tin, int rowC, int ldc, int mode)
{
    extern __shared__ char dsm[];
    __shared__ float s_sum[128], s_sq[128];
    uint32_t sbase = smem_u32(dsm);
    int tid = threadIdx.x, lane = tid & 31, wid = tid >> 5;
    int m0 = blockIdx.y * 128, n0 = blockIdx.x * 128;

    long long gA[2], gB[2];
    uint32_t so[2];
    #pragma unroll
    for (int p = 0; p < 2; ++p) {
        int row = p*64 + (tid >> 2);
        int seg = tid & 3;
        int rg = m0 + row;
        gA[p] = (long long)((rg / Tout) * Tin + (rg % Tout)) * rowC + seg*8;
        gB[p] = (long long)(n0 + row) * K + seg*8;
        so[p] = (uint32_t)(row*LDS_STRIDE + seg*8) * 2;
    }

    int wm = wid & 1, wn = wid >> 1;
    uint32_t aoff = (uint32_t)((wm*64 + (lane & 15))*LDS_STRIDE + (lane >> 4)*8) * 2;
    uint32_t boff = (uint32_t)((wn*32 + ((lane >> 4) & 1)*8 + (lane & 7))*LDS_STRIDE
                               + ((lane >> 3) & 1)*8) * 2;

    float acc[4][4][4] = {};

    int nc = K >> 5;
    {
        uint32_t st = sbase;
        #pragma unroll
        for (int p = 0; p < 2; ++p) {
            CP16(st +              so[p], (const char*)Ah + gA[p]*2);
            CP16(st + ARR_BYTES  + so[p], (const char*)Al + gA[p]*2);
            CP16(st + 2*ARR_BYTES+ so[p], (const char*)Bh + gB[p]*2);
            CP16(st + 3*ARR_BYTES+ so[p], (const char*)Bl + gB[p]*2);
        }
    }
    CP_COMMIT();

    for (int c = 0; c < nc; ++c) {
        if (c + 1 < nc) {
            uint32_t st = sbase + ((c+1) & 1)*STAGE_BYTES;
            long long k0 = (long long)(c+1)*KC;
            #pragma unroll
            for (int p = 0; p < 2; ++p) {
                CP16(st +              so[p], (const char*)Ah + (gA[p]+k0)*2);
                CP16(st + ARR_BYTES  + so[p], (const char*)Al + (gA[p]+k0)*2);
                CP16(st + 2*ARR_BYTES+ so[p], (const char*)Bh + (gB[p]+k0)*2);
                CP16(st + 3*ARR_BYTES+ so[p], (const char*)Bl + (gB[p]+k0)*2);
            }
        }
        CP_COMMIT();
        CP_WAIT1();
        __syncthreads();

        uint32_t st = sbase + (c & 1)*STAGE_BYTES;
        uint32_t aAh = st + aoff,               aAl = st + ARR_BYTES   + aoff;
        uint32_t aBh = st + 2*ARR_BYTES + boff, aBl = st + 3*ARR_BYTES + boff;

        #pragma unroll
        for (int k16 = 0; k16 < 2; ++k16) {
            uint32_t kb = k16 * 32;
            uint32_t ah[4][4], al[4][4];
            #pragma unroll
            for (int i = 0; i < 4; ++i) {
                LDSM_X4(ah[i][0], ah[i][1], ah[i][2], ah[i][3], aAh + kb + i*(16*LDS_STRIDE*2));
                LDSM_X4(al[i][0], al[i][1], al[i][2], al[i][3], aAl + kb + i*(16*LDS_STRIDE*2));
            }
            #pragma unroll
            for (int jj = 0; jj < 2; ++jj) {
                uint32_t bh2[2][2], bl2[2][2];
                uint32_t t0, t1, t2, t3;
                LDSM_X4(t0, t1, t2, t3, aBh + kb + jj*(16*LDS_STRIDE*2));
                bh2[0][0] = t0; bh2[0][1] = t1; bh2[1][0] = t2; bh2[1][1] = t3;
                LDSM_X4(t0, t1, t2, t3, aBl + kb + jj*(16*LDS_STRIDE*2));
                bl2[0][0] = t0; bl2[0][1] = t1; bl2[1][0] = t2; bl2[1][1] = t3;
                #pragma unroll
                for (int i = 0; i < 4; ++i)
                    #pragma unroll
                    for (int j2 = 0; j2 < 2; ++j2) {
                        MMA16816(acc[i][jj*2+j2], ah[i], bh2[j2]);
                        MMA16816(acc[i][jj*2+j2], ah[i], bl2[j2]);
                        MMA16816(acc[i][jj*2+j2], al[i], bh2[j2]);
                    }
            }
        }
        __syncthreads();
    }

    if (mode == 3) {
        if (tid < 128) { s_sum[tid] = 0.f; s_sq[tid] = 0.f; }
        __syncthreads();
    }

    float psum[8] = {}, psq[8] = {};
    int rbase = m0 + wm*64 + (lane >> 2);
    int cbase = n0 + wn*32 + (lane & 3)*2;
    #pragma unroll
    for (int i = 0; i < 4; ++i) {
        #pragma unroll
        for (int j = 0; j < 4; ++j) {
            int gc = cbase + j*8;
            #pragma unroll
            for (int half = 0; half < 2; ++half) {
                long long gr = rbase + i*16 + half*8;
                float v0 = acc[i][j][half*2], v1 = acc[i][j][half*2 + 1];
                long long idx = gr * ldc + gc;
                if (mode == 2) {
                    v0 = fmaxf(v0 + bias[gc], 0.f);
                    v1 = fmaxf(v1 + bias[gc+1], 0.f);
                    split_store(Chi, Clo, idx, v0, v1);
                } else {
                    *(float2*)&Cf[idx] = make_float2(v0, v1);
                    if (mode == 3) {
                        psum[j*2]   += v0;  psq[j*2]   += v0*v0;
                        psum[j*2+1] += v1;  psq[j*2+1] += v1*v1;
                    }
                }
            }
        }
    }

    if (mode == 3) {
        int lc = wn*32 + (lane & 3)*2;
        #pragma unroll
        for (int j = 0; j < 4; ++j) {
            atomicAdd(&s_sum[lc + j*8],     psum[j*2]);
            atomicAdd(&s_sum[lc + j*8 + 1], psum[j*2+1]);
            atomicAdd(&s_sq[lc + j*8],      psq[j*2]);
            atomicAdd(&s_sq[lc + j*8 + 1],  psq[j*2+1]);
        }
        __syncthreads();
        if (tid < 128) {
            atomicAdd(&g_s2[n0 + tid],  s_sum[tid]);
            atomicAdd(&g_sq2[n0 + tid], s_sq[tid]);
        }
    }
}

// ---------------- pool / BN3 / tail ----------------
__global__ void k_pool(const float* __restrict__ g2w, const float* __restrict__ b2w) {
    int c = threadIdx.x;
    int chunk = blockIdx.x;
    int tp = blockIdx.y;
    int g = blockIdx.z;
    float mu  = g_s2[c]  * (1.f/62464.f);
    float var = g_sq2[c] * (1.f/62464.f) - mu*mu;
    float a = g2w[c] * rsqrtf(var + EPSV);
    float bb = b2w[c] - mu*a;
    float acc = 0.f;
    for (int nl = 0; nl < 16; ++nl) {
        int n = g*64 + chunk*16 + nl;
        const float* p = &g_y2[(n*122 + tp*4)*128 + c];
        float s4 = p[0] + p[128] + p[256] + p[384];
        acc += fmaxf(a * (s4 * 0.25f) + bb, 0.f);
    }
    atomicAdd(&g_gbuf[(g*30 + tp)*128 + c], acc * (1.f/64.f));
}

__global__ void k_bn3stats() {
    __shared__ float red[256];
    int tid = threadIdx.x;
    int c = tid & 127, r0 = tid >> 7;
    float ls = 0.f, lq = 0.f;
    for (int r = r0; r < 224; r += 2) { float v = g_y3[r*128 + c]; ls += v; lq += v*v; }
    red[tid] = ls; __syncthreads();
    float ssum = 0.f;
    if (tid < 128) ssum = red[tid] + red[tid+128];
    __syncthreads();
    red[tid] = lq; __syncthreads();
    if (tid < 128) {
        float q = red[tid] + red[tid+128];
        float mu = ssum * (1.f/224.f);
        float var = q * (1.f/224.f) - mu*mu;
        g_mu3[tid] = mu;
        g_rs3[tid] = rsqrtf(var + EPSV);
    }
}

__global__ void k_tail(const float* __restrict__ g3w, const float* __restrict__ b3w,
                       const float* __restrict__ Wd, const float* __restrict__ bd,
                       float* __restrict__ out) {
    __shared__ float gg[896];
    __shared__ float slog[4];
    int b = blockIdx.x, tid = threadIdx.x;
    int c = tid;
    float a = g3w[c] * g_rs3[c];
    float bb = b3w[c] - g_mu3[c]*a;
    #pragma unroll
    for (int tp = 0; tp < 7; ++tp) {
        const float* p = &g_y3[(b*28 + tp*4)*128 + c];
        float s4 = (p[0] + p[128] + p[256] + p[384]) * 0.25f;
        gg[tp*128 + c] = fmaxf(a*s4 + bb, 0.f);
    }
    __syncthreads();
    int w = tid >> 5, lane = tid & 31;
    float s = 0.f;
    for (int i = lane; i < 896; i += 32) s += gg[i] * Wd[i*4 + w];
    #pragma unroll
    for (int off = 16; off; off >>= 1) s += __shfl_xor_sync(0xffffffffu, s, off);
    if (lane == 0) slog[w] = s + bd[w];
    __syncthreads();
    if (tid == 0) {
        float m = fmaxf(fmaxf(slog[0], slog[1]), fmaxf(slog[2], slog[3]));
        float se = expf(slog[0]-m)+expf(slog[1]-m)+expf(slog[2]-m)+expf(slog[3]-m);
        float lse = logf(se);
        #pragma unroll
        for (int j = 0; j < 4; ++j) out[b*4 + j] = slog[j] - m - lse;
    }
}

// ---------------- launch ----------------
extern "C" void kernel_launch(void* const* d_in, const int* in_sizes, int n_in,
                              void* d_out, int out_size) {
    const float* x   = (const float*)d_in[0];
    const float* pos = (const float*)d_in[1];
    const int*   ei  = (const int*)d_in[2];
    const float* W1  = (const float*)d_in[4];
    const float* g1  = (const float*)d_in[5];
    const float* b1  = (const float*)d_in[6];
    const float* Wp1 = (const float*)d_in[7];
    const float* bp1 = (const float*)d_in[8];
    const float* Wp2 = (const float*)d_in[9];
    const float* bp2 = (const float*)d_in[10];
    const float* Wg1 = (const float*)d_in[11];
    const float* bg1 = (const float*)d_in[12];
    const float* Wg2 = (const float*)d_in[13];
    const float* bg2 = (const float*)d_in[14];
    const float* W2  = (const float*)d_in[15];
    const float* g2  = (const float*)d_in[16];
    const float* b2  = (const float*)d_in[17];
    const float* W3  = (const float*)d_in[18];
    const float* g3  = (const float*)d_in[19];
    const float* b3  = (const float*)d_in[20];
    const float* Wd  = (const float*)d_in[21];
    const float* bd  = (const float*)d_in[22];
    float* out = (float*)d_out;

    float *pY2, *pGbuf, *pY3;
    __nv_bfloat16 *pH0h, *pH0l, *pA0h, *pA0l, *pH1h, *pH1l, *pA1h, *pA1l, *pH2h, *pH2l;
    __nv_bfloat16 *pWg1h, *pWg1l, *pWg2h, *pWg2l, *pW2h, *pW2l;
    cudaGetSymbolAddress((void**)&pY2,   g_y2);
    cudaGetSymbolAddress((void**)&pGbuf, g_gbuf);
    cudaGetSymbolAddress((void**)&pY3,   g_y3);
    cudaGetSymbolAddress((void**)&pH0h,  g_h0h);
    cudaGetSymbolAddress((void**)&pH0l,  g_h0l);
    cudaGetSymbolAddress((void**)&pA0h,  g_agg0h);
    cudaGetSymbolAddress((void**)&pA0l,  g_agg0l);
    cudaGetSymbolAddress((void**)&pH1h,  g_h1h);
    cudaGetSymbolAddress((void**)&pH1l,  g_h1l);
    cudaGetSymbolAddress((void**)&pA1h,  g_agg1h);
    cudaGetSymbolAddress((void**)&pA1l,  g_agg1l);
    cudaGetSymbolAddress((void**)&pH2h,  g_h2h);
    cudaGetSymbolAddress((void**)&pH2l,  g_h2l);
    cudaGetSymbolAddress((void**)&pWg1h, g_Wg1th);
    cudaGetSymbolAddress((void**)&pWg1l, g_Wg1tl);
    cudaGetSymbolAddress((void**)&pWg2h, g_Wg2th);
    cudaGetSymbolAddress((void**)&pWg2l, g_Wg2tl);
    cudaGetSymbolAddress((void**)&pW2h,  g_W2th);
    cudaGetSymbolAddress((void**)&pW2l,  g_W2tl);

    const int DSM = 2*STAGE_BYTES;   // 81920
    cudaFuncSetAttribute(k_gemm_tc, cudaFuncAttributeMaxDynamicSharedMemorySize, DSM);
    cudaFuncSetAttribute(k_agg_tc, cudaFuncAttributeMaxDynamicSharedMemorySize, AGG_SMEM);

    k_zero<<<128, 256>>>();
    k_deg<<<16, 256>>>(ei);
    k_adj<<<18, 256>>>(ei);
    k_wprep<<<1344, 256>>>(Wg1, Wg2, W2);
    k_pe<<<512, 64>>>(pos, Wp1, bp1, Wp2, bp2);
    k_conv1stats<<<1024, 256>>>(x, W1);
    k_bn1pe<<<1024, 256>>>(x, W1, g1, b1);

    // agg0 = A @ h0  (TC, split out), F = T*C0 = 8192
    k_agg_tc<<<dim3(32, 8), 256, AGG_SMEM>>>(pH0h, pH0l, pA0h, pA0l, 8192);
    // gcn1: h1 = relu(agg0 @ Wg1^T + bg1)  (TC, split out)
    k_gemm_tc<<<dim3(2, 512), 256, DSM>>>(pA0h, pA0l, pWg1h, pWg1l, bg1,
                                          nullptr, pH1h, pH1l,
                                          64, 65536, 65536, 64, 256, 2);
    // agg1 = A @ h1  (TC, split out), F = T*EMB = 32768
    k_agg_tc<<<dim3(128, 8), 256, AGG_SMEM>>>(pH1h, pH1l, pA1h, pA1l, 32768);
    // gcn2: h2 = relu(agg1 @ Wg2^T + bg2)  (TC, split out)
    k_gemm_tc<<<dim3(2, 512), 256, DSM>>>(pA1h, pA1l, pWg2h, pWg2l, bg2,
                                          nullptr, pH2h, pH2l,
                                          256, 65536, 65536, 256, 256, 2);
    // conv2 (k=7 VALID, 256->128) implicit GEMM (TC, fp32 out + fused BN2 stats)
    k_gemm_tc<<<dim3(1, 488), 256, DSM>>>(pH2h, pH2l, pW2h, pW2l, nullptr,
                                          pY2, nullptr, nullptr,
                                          1792, 122, 128, 256, 128, 3);
    k_pool<<<dim3(4, 30, 8), 128>>>(g2, b2);
    // conv3 (k=3 VALID, 128->128) SIMT
    k_gemm<<<dim3(2, 4, 1), 256>>>(pGbuf, W3, pY3, 224, 128, 384, 28, 30, 128);
    k_bn3stats<<<1, 256>>>();
    k_tail<<<8, 128>>>(g3, b3, Wd, bd, out);
}

// round 9
// speedup vs baseline: 1.9208x; 1.1122x over previous
#include <cuda_runtime.h>
#include <cuda_bf16.h>
#include <math.h>
#include <stdint.h>

#define N_NODES 512
#define TT 128
#define NE 4096
#define C0 64
#define C1 128
#define C2 128
#define EMB 256
#define NG 8
#define EPSV 1e-5f

// ---------------- scratch (device globals; no allocs allowed) ----------------
__device__ float g_y2[N_NODES*122*C1];
__device__ float g_gbuf[NG*30*C1];
__device__ float g_y3[NG*28*C2];
__device__ float g_pe[N_NODES*C0];
__device__ float g_A[NG*64*64];
__device__ int   g_deg[N_NODES];
__device__ float g_s1[C0], g_sq1[C0];
__device__ float g_s2[C1], g_sq2[C1];
__device__ float g_mu3[C2], g_rs3[C2];

// bf16 split buffers
__device__ __nv_bfloat16 g_Ash[NG*64*64],        g_Asl[NG*64*64];
__device__ __nv_bfloat16 g_h0h[N_NODES*TT*C0],   g_h0l[N_NODES*TT*C0];
__device__ __nv_bfloat16 g_agg0h[N_NODES*TT*C0], g_agg0l[N_NODES*TT*C0];
__device__ __nv_bfloat16 g_h1h[N_NODES*TT*EMB],  g_h1l[N_NODES*TT*EMB];
__device__ __nv_bfloat16 g_agg1h[N_NODES*TT*EMB],g_agg1l[N_NODES*TT*EMB];
__device__ __nv_bfloat16 g_h2h[N_NODES*TT*EMB],  g_h2l[N_NODES*TT*EMB];
__device__ __nv_bfloat16 g_Wg1th[EMB*C0],  g_Wg1tl[EMB*C0];     // [256][64]
__device__ __nv_bfloat16 g_Wg2th[EMB*EMB], g_Wg2tl[EMB*EMB];    // [256][256]
__device__ __nv_bfloat16 g_W2th[C1*7*EMB], g_W2tl[C1*7*EMB];    // [128][1792]

// ---------------- helpers ----------------
__device__ __forceinline__ uint32_t smem_u32(const void* p) {
    uint32_t a;
    asm("{ .reg .u64 t; cvta.to.shared.u64 t, %1; cvt.u32.u64 %0, t; }" : "=r"(a) : "l"(p));
    return a;
}
#define CP16(dst, src) asm volatile("cp.async.cg.shared.global [%0], [%1], 16;" :: "r"(dst), "l"(src))
#define CP_COMMIT()    asm volatile("cp.async.commit_group;" ::: "memory")
#define CP_WAITG1()    asm volatile("cp.async.wait_group 1;" ::: "memory")
#define CP_WAIT0()     asm volatile("cp.async.wait_group 0;" ::: "memory")
#define LDSM_X4(r0, r1, r2, r3, addr) \
    asm volatile("ldmatrix.sync.aligned.m8n8.x4.shared.b16 {%0,%1,%2,%3}, [%4];" \
        : "=r"(r0), "=r"(r1), "=r"(r2), "=r"(r3) : "r"(addr))
#define LDSM_X4T(r0, r1, r2, r3, addr) \
    asm volatile("ldmatrix.sync.aligned.m8n8.x4.trans.shared.b16 {%0,%1,%2,%3}, [%4];" \
        : "=r"(r0), "=r"(r1), "=r"(r2), "=r"(r3) : "r"(addr))
#define MMA16816(d, a, b) \
    asm volatile("mma.sync.aligned.m16n8k16.row.col.f32.bf16.bf16.f32 " \
        "{%0,%1,%2,%3}, {%4,%5,%6,%7}, {%8,%9}, {%0,%1,%2,%3};" \
        : "+f"((d)[0]), "+f"((d)[1]), "+f"((d)[2]), "+f"((d)[3]) \
        : "r"((a)[0]), "r"((a)[1]), "r"((a)[2]), "r"((a)[3]), "r"((b)[0]), "r"((b)[1]))

__device__ __forceinline__ void split_store(__nv_bfloat16* H, __nv_bfloat16* L,
                                            long long idx, float v0, float v1) {
    __nv_bfloat16 h0 = __float2bfloat16(v0), h1 = __float2bfloat16(v1);
    __nv_bfloat162 hv; hv.x = h0; hv.y = h1;
    __nv_bfloat162 lv;
    lv.x = __float2bfloat16(v0 - __bfloat162float(h0));
    lv.y = __float2bfloat16(v1 - __bfloat162float(h1));
    *(__nv_bfloat162*)&H[idx] = hv;
    *(__nv_bfloat162*)&L[idx] = lv;
}

__device__ __forceinline__ void split1(float v, __nv_bfloat16* H, __nv_bfloat16* L, int idx) {
    __nv_bfloat16 h = __float2bfloat16(v);
    H[idx] = h;
    L[idx] = __float2bfloat16(v - __bfloat162float(h));
}

// ---------------- setup kernels ----------------
__global__ void k_zero() {
    int i = blockIdx.x*256 + threadIdx.x;
    if (i < NG*64*64) g_A[i] = 0.f;
    if (i < N_NODES)  g_deg[i] = 0;
    if (i < C0) { g_s1[i]=0.f; g_sq1[i]=0.f; }
    if (i < C1) { g_s2[i]=0.f; g_sq2[i]=0.f; }
    if (i < NG*30*C1) g_gbuf[i] = 0.f;
}

__global__ void k_deg(const int* __restrict__ ei) {
    int e = blockIdx.x*256 + threadIdx.x;
    if (e < NE) atomicAdd(&g_deg[ei[NE + e]], 1);
}

__global__ void k_adj(const int* __restrict__ ei) {
    int i = blockIdx.x*256 + threadIdx.x;
    if (i < NE) {
        int s = ei[i], d = ei[NE + i];
        float nr = rsqrtf((float)(g_deg[s]+1)) * rsqrtf((float)(g_deg[d]+1));
        int g = d >> 6;
        atomicAdd(&g_A[(g<<12) + ((d&63)<<6) + (s&63)], nr);
    } else if (i < NE + N_NODES) {
        int n = i - NE;
        float di = 1.f / (float)(g_deg[n]+1);
        atomicAdd(&g_A[((n>>6)<<12) + ((n&63)<<6) + (n&63)], di);
    }
}

// fused weight/adjacency prep: Wg1t, Wg2t, W2t transposed splits + A split
__global__ void k_wprep(const float* __restrict__ Wg1, const float* __restrict__ Wg2,
                        const float* __restrict__ W2) {
    int i = blockIdx.x*256 + threadIdx.x;
    if (i < 16384) {
        int n = i >> 6, k = i & 63;
        split1(Wg1[k*256 + n], g_Wg1th, g_Wg1tl, i);
    } else if (i < 81920) {
        int j = i - 16384;
        int n = j >> 8, k = j & 255;
        split1(Wg2[k*256 + n], g_Wg2th, g_Wg2tl, j);
    } else if (i < 311296) {
        int j = i - 81920;
        int n = j / 1792, k = j - n*1792;
        split1(W2[k*128 + n], g_W2th, g_W2tl, j);
    } else if (i < 344064) {
        int j = i - 311296;
        split1(g_A[j], g_Ash, g_Asl, j);
    }
}

__global__ void k_pe(const float* __restrict__ pos, const float* __restrict__ Wp1,
                     const float* __restrict__ bp1, const float* __restrict__ Wp2,
                     const float* __restrict__ bp2) {
    __shared__ float t1[64];
    int n = blockIdx.x, j = threadIdx.x;
    float p0 = pos[n*3], p1 = pos[n*3+1], p2 = pos[n*3+2];
    t1[j] = fmaxf(p0*Wp1[j] + p1*Wp1[64+j] + p2*Wp1[128+j] + bp1[j], 0.f);
    __syncthreads();
    float s = bp2[j];
    #pragma unroll 8
    for (int k = 0; k < 64; ++k) s += t1[k]*Wp2[k*64 + j];
    g_pe[n*64 + j] = s;
}

// conv1 BN statistics only (y1 never materialized; recomputed in k_bn1pe)
__global__ void k_conv1stats(const float* __restrict__ x, const float* __restrict__ W1) {
    __shared__ float sx[70];
    __shared__ float red[256];
    int b = blockIdx.x;
    int n = b >> 1;
    int t0 = (b & 1) * 64;
    int tid = threadIdx.x;
    if (tid < 70) {
        int t = t0 - 3 + tid;
        sx[tid] = (t >= 0 && t < TT) ? x[n*TT + t] : 0.f;
    }
    __syncthreads();
    int c = tid & 63, r0 = tid >> 6;
    float w[7];
    #pragma unroll
    for (int k = 0; k < 7; ++k) w[k] = W1[k*64 + c];
    float ls = 0.f, lq = 0.f;
    for (int rr = r0; rr < 64; rr += 4) {
        float y = 0.f;
        #pragma unroll
        for (int k = 0; k < 7; ++k) y += sx[rr + k] * w[k];
        ls += y; lq += y*y;
    }
    red[tid] = ls; __syncthreads();
    if (tid < 64) atomicAdd(&g_s1[c], red[tid]+red[tid+64]+red[tid+128]+red[tid+192]);
    __syncthreads();
    red[tid] = lq; __syncthreads();
    if (tid < 64) atomicAdd(&g_sq1[c], red[tid]+red[tid+64]+red[tid+128]+red[tid+192]);
}

// recompute conv1 + BN1 apply + ReLU + add pe -> h0 bf16 split
__global__ void k_bn1pe(const float* __restrict__ x, const float* __restrict__ W1,
                        const float* __restrict__ g1w, const float* __restrict__ b1w) {
    __shared__ float sx[70];
    int b = blockIdx.x;
    int n = b >> 1;
    int t0 = (b & 1) * 64;
    int tid = threadIdx.x;
    if (tid < 70) {
        int t = t0 - 3 + tid;
        sx[tid] = (t >= 0 && t < TT) ? x[n*TT + t] : 0.f;
    }
    __syncthreads();
    int c0 = (tid & 31) * 2;
    int r0 = tid >> 5;
    float w0[7], w1[7];
    #pragma unroll
    for (int k = 0; k < 7; ++k) { w0[k] = W1[k*64 + c0]; w1[k] = W1[k*64 + c0 + 1]; }
    float mu0  = g_s1[c0]   * (1.f/65536.f);
    float var0 = g_sq1[c0]  * (1.f/65536.f) - mu0*mu0;
    float a0 = g1w[c0] * rsqrtf(var0 + EPSV);
    float bb0 = b1w[c0] - mu0*a0;
    float mu1  = g_s1[c0+1]  * (1.f/65536.f);
    float var1 = g_sq1[c0+1] * (1.f/65536.f) - mu1*mu1;
    float a1 = g1w[c0+1] * rsqrtf(var1 + EPSV);
    float bb1 = b1w[c0+1] - mu1*a1;
    float pe0 = g_pe[n*64 + c0], pe1 = g_pe[n*64 + c0 + 1];
    for (int r = r0; r < 64; r += 8) {
        float y0 = 0.f, y1 = 0.f;
        #pragma unroll
        for (int k = 0; k < 7; ++k) { y0 += sx[r+k]*w0[k]; y1 += sx[r+k]*w1[k]; }
        float v0 = fmaxf(a0*y0 + bb0, 0.f) + pe0;
        float v1 = fmaxf(a1*y1 + bb1, 0.f) + pe1;
        split_store(g_h0h, g_h0l, (long long)(b*64 + r)*64 + c0, v0, v1);
    }
}

// ---------------- fp32 SIMT GEMM (conv3 only) ----------------
__global__ void k_gemm(const float* __restrict__ Aall, const float* __restrict__ Ball,
                       float* __restrict__ Call,
                       int M, int N, int K, int Tout, int Tin, int rowC)
{
    const float* A = Aall;
    const float* B = Ball;

    __shared__ __align__(16) float As[16][68];
    __shared__ __align__(16) float Bs[16][68];

    int tid = threadIdx.x;
    int tx = tid & 15, ty = tid >> 4;
    int m0 = blockIdx.y * 64;
    int n0 = blockIdx.x * 64;

    int abase[4]; bool aok[4];
    #pragma unroll
    for (int p = 0; p < 4; ++p) {
        int row = m0 + p*16 + (tid >> 4);
        aok[p] = (row < M);
        abase[p] = aok[p] ? ((row / Tout) * Tin + (row % Tout)) * rowC : 0;
    }
    int akk = tid & 15;

    float acc[4][4] = {};

    for (int k0 = 0; k0 < K; k0 += 16) {
        #pragma unroll
        for (int p = 0; p < 4; ++p) {
            float v = aok[p] ? A[abase[p] + k0 + akk] : 0.f;
            As[akk][p*16 + (tid >> 4)] = v;
        }
        #pragma unroll
        for (int p = 0; p < 4; ++p) {
            int kk = p*4 + (tid >> 6);
            Bs[kk][tid & 63] = B[(k0 + kk) * N + n0 + (tid & 63)];
        }
        __syncthreads();
        #pragma unroll
        for (int kk = 0; kk < 16; ++kk) {
            float4 av = *(const float4*)&As[kk][ty*4];
            float4 bv = *(const float4*)&Bs[kk][tx*4];
            float a_[4] = {av.x, av.y, av.z, av.w};
            float b_[4] = {bv.x, bv.y, bv.z, bv.w};
            #pragma unroll
            for (int i = 0; i < 4; ++i)
                #pragma unroll
                for (int j = 0; j < 4; ++j)
                    acc[i][j] += a_[i] * b_[j];
        }
        __syncthreads();
    }

    #pragma unroll
    for (int i = 0; i < 4; ++i) {
        int row = m0 + ty*4 + i;
        if (row >= M) continue;
        #pragma unroll
        for (int j = 0; j < 4; ++j) {
            int col = n0 + tx*4 + j;
            Call[(long long)row * N + col] = acc[i][j];
        }
    }
}

// ---------------- TC aggregation: O = A(64x64) @ H(64xF) per graph -----------
#define ASTR 72
#define HSTR 264
#define AGG_SMEM (2*64*ASTR*2 + 2*64*HSTR*2)   // 86016

__global__ void __launch_bounds__(256, 2)
k_agg_tc(const __nv_bfloat16* __restrict__ Hh, const __nv_bfloat16* __restrict__ Hl,
         __nv_bfloat16* __restrict__ Oh, __nv_bfloat16* __restrict__ Ol, int F)
{
    extern __shared__ char dsm[];
    uint32_t sAh = smem_u32(dsm);
    uint32_t sAl = sAh + 64*ASTR*2;
    uint32_t sHh = sAl + 64*ASTR*2;
    uint32_t sHl = sHh + 64*HSTR*2;

    int g = blockIdx.y;
    int n0 = blockIdx.x * 256;
    int tid = threadIdx.x, lane = tid & 31, wid = tid >> 5;

    const char* Agh = (const char*)(g_Ash + g*4096);
    const char* Agl = (const char*)(g_Asl + g*4096);
    #pragma unroll
    for (int it = 0; it < 2; ++it) {
        int sid = it*256 + tid;
        int row = sid >> 3, seg = (sid & 7) * 8;
        CP16(sAh + (row*ASTR + seg)*2, Agh + (row*64 + seg)*2);
        CP16(sAl + (row*ASTR + seg)*2, Agl + (row*64 + seg)*2);
    }
    long long hbase = (long long)(g*64) * F + n0;
    #pragma unroll
    for (int it = 0; it < 8; ++it) {
        int sid = it*256 + tid;
        int row = sid >> 5, seg = (sid & 31) * 8;
        long long go = (hbase + (long long)row*F + seg) * 2;
        CP16(sHh + (row*HSTR + seg)*2, (const char*)Hh + go);
        CP16(sHl + (row*HSTR + seg)*2, (const char*)Hl + go);
    }
    CP_COMMIT();
    CP_WAIT0();
    __syncthreads();

    float acc[4][4][4] = {};
    int nw = wid * 32;
    uint32_t arow = lane & 15, ahi = (lane >> 4) * 8;

    #pragma unroll
    for (int kk = 0; kk < 4; ++kk) {
        uint32_t ah[4][4], al[4][4];
        uint32_t acol = kk*16 + ahi;
        #pragma unroll
        for (int i = 0; i < 4; ++i) {
            LDSM_X4(ah[i][0], ah[i][1], ah[i][2], ah[i][3],
                    sAh + ((i*16 + arow)*ASTR + acol)*2);
            LDSM_X4(al[i][0], al[i][1], al[i][2], al[i][3],
                    sAl + ((i*16 + arow)*ASTR + acol)*2);
        }
        uint32_t brow = kk*16 + (lane & 15);
        #pragma unroll
        for (int jp = 0; jp < 2; ++jp) {
            uint32_t bh2[2][2], bl2[2][2];
            uint32_t bcol = nw + jp*16 + ahi;
            uint32_t t0, t1, t2, t3;
            LDSM_X4T(t0, t1, t2, t3, sHh + (brow*HSTR + bcol)*2);
            bh2[0][0] = t0; bh2[0][1] = t1; bh2[1][0] = t2; bh2[1][1] = t3;
            LDSM_X4T(t0, t1, t2, t3, sHl + (brow*HSTR + bcol)*2);
            bl2[0][0] = t0; bl2[0][1] = t1; bl2[1][0] = t2; bl2[1][1] = t3;
            #pragma unroll
            for (int i = 0; i < 4; ++i)
                #pragma unroll
                for (int j2 = 0; j2 < 2; ++j2) {
                    MMA16816(acc[i][jp*2+j2], ah[i], bh2[j2]);
                    MMA16816(acc[i][jp*2+j2], ah[i], bl2[j2]);
                    MMA16816(acc[i][jp*2+j2], al[i], bh2[j2]);
                }
        }
    }

    int rb = lane >> 2;
    int cb = n0 + nw + (lane & 3)*2;
    #pragma unroll
    for (int i = 0; i < 4; ++i)
        #pragma unroll
        for (int j = 0; j < 4; ++j)
            #pragma unroll
            for (int half = 0; half < 2; ++half) {
                int row = i*16 + rb + half*8;
                long long idx = (long long)(g*64 + row) * F + cb + j*8;
                split_store(Oh, Ol, idx, acc[i][j][half*2], acc[i][j][half*2+1]);
            }
}

// ---------------- bf16-split tensor-core GEMM via mma.sync --------------------
// 3-stage cp.async ring, ONE __syncthreads per 32-k chunk.
// SMEM layout: zero-padded 64B rows (32 halves) with XOR swizzle on 16B chunks:
// phys_chunk = logical_chunk ^ ((row>>1)&3). All addresses 16B aligned.
// mode 0: fp32 store; 2: bias+relu -> bf16 split store; 3: fp32 store + BN2 stats
#define KC 32
#define ROWB 64                             // bytes per row (32 halves)
#define ARR_BYTES (128*ROWB)                // 8192
#define STAGE_BYTES (4*ARR_BYTES)           // 32768
#define NSTAGE 3

__global__ void __launch_bounds__(256, 2)
k_gemm_tc(const __nv_bfloat16* __restrict__ Ah, const __nv_bfloat16* __restrict__ Al,
          const __nv_bfloat16* __restrict__ Bh, const __nv_bfloat16* __restrict__ Bl,
          const float* __restrict__ bias,
          float* __restrict__ Cf, __nv_bfloat16* __restrict__ Chi, __nv_bfloat16* __restrict__ Clo,
          int K, int Tout, int Tin, int rowC, int ldc, int mode)
{
    extern __shared__ char dsm[];
    __shared__ float s_sum[128], s_sq[128];
    uint32_t sbase = smem_u32(dsm);
    int tid = threadIdx.x, lane = tid & 31, wid = tid >> 5;
    int m0 = blockIdx.y * 128, n0 = blockIdx.x * 128;

    // copy geometry: row = p*64 + tid/4, logical seg = tid&3 (16B each)
    long long gA[2], gB[2];
    uint32_t so[2];
    #pragma unroll
    for (int p = 0; p < 2; ++p) {
        int row = p*64 + (tid >> 2);
        int seg = tid & 3;
        int pseg = seg ^ ((row >> 1) & 3);
        int rg = m0 + row;
        gA[p] = (long long)((rg / Tout) * Tin + (rg % Tout)) * rowC + seg*8;
        gB[p] = (long long)(n0 + row) * K + seg*8;
        so[p] = (uint32_t)(row*ROWB + pseg*16);
    }

    // warp tile + fragment addressing (swizzle-aware)
    int wm = wid & 1, wn = wid >> 1;
    uint32_t aRowB = (uint32_t)(wm*64 + (lane & 15)) * ROWB;     // + i*16*ROWB
    uint32_t aSub  = lane >> 4;                                   // 0/1
    uint32_t xorA  = ((lane & 15) >> 1) & 3;
    uint32_t bRowB = (uint32_t)(wn*32 + ((lane >> 4) & 1)*8 + (lane & 7)) * ROWB;
    uint32_t bSub  = (lane >> 3) & 1;
    uint32_t xorB  = ((lane & 7) >> 1) & 3;

    float acc[4][4][4] = {};

    int nc = K >> 5;
    // prologue: chunks 0,1 -> stages 0,1
    #pragma unroll
    for (int pc = 0; pc < 2; ++pc) {
        uint32_t st = sbase + pc*STAGE_BYTES;
        long long k0 = (long long)pc*KC;
        #pragma unroll
        for (int p = 0; p < 2; ++p) {
            CP16(st +              so[p], (const char*)Ah + (gA[p]+k0)*2);
            CP16(st + ARR_BYTES  + so[p], (const char*)Al + (gA[p]+k0)*2);
            CP16(st + 2*ARR_BYTES+ so[p], (const char*)Bh + (gB[p]+k0)*2);
            CP16(st + 3*ARR_BYTES+ so[p], (const char*)Bl + (gB[p]+k0)*2);
        }
        CP_COMMIT();
    }

    int scur = 0, snext2 = 2;
    for (int c = 0; c < nc; ++c) {
        CP_WAITG1();
        __syncthreads();

        if (c + 2 < nc) {
            uint32_t st = sbase + snext2*STAGE_BYTES;
            long long k0 = (long long)(c+2)*KC;
            #pragma unroll
            for (int p = 0; p < 2; ++p) {
                CP16(st +              so[p], (const char*)Ah + (gA[p]+k0)*2);
                CP16(st + ARR_BYTES  + so[p], (const char*)Al + (gA[p]+k0)*2);
                CP16(st + 2*ARR_BYTES+ so[p], (const char*)Bh + (gB[p]+k0)*2);
                CP16(st + 3*ARR_BYTES+ so[p], (const char*)Bl + (gB[p]+k0)*2);
            }
        }
        CP_COMMIT();

        uint32_t st = sbase + scur*STAGE_BYTES;

        #pragma unroll
        for (int k16 = 0; k16 < 2; ++k16) {
            uint32_t physA = (((uint32_t)k16*2 + aSub) ^ xorA) * 16;
            uint32_t physB = (((uint32_t)k16*2 + bSub) ^ xorB) * 16;
            uint32_t ah[4][4], al[4][4];
            #pragma unroll
            for (int i = 0; i < 4; ++i) {
                uint32_t ro = aRowB + i*(16*ROWB) + physA;
                LDSM_X4(ah[i][0], ah[i][1], ah[i][2], ah[i][3], st + ro);
                LDSM_X4(al[i][0], al[i][1], al[i][2], al[i][3], st + ARR_BYTES + ro);
            }
            #pragma unroll
            for (int jj = 0; jj < 2; ++jj) {
                uint32_t bh2[2][2], bl2[2][2];
                uint32_t ro = bRowB + jj*(16*ROWB) + physB;
                uint32_t t0, t1, t2, t3;
                LDSM_X4(t0, t1, t2, t3, st + 2*ARR_BYTES + ro);
                bh2[0][0] = t0; bh2[0][1] = t1; bh2[1][0] = t2; bh2[1][1] = t3;
                LDSM_X4(t0, t1, t2, t3, st + 3*ARR_BYTES + ro);
                bl2[0][0] = t0; bl2[0][1] = t1; bl2[1][0] = t2; bl2[1][1] = t3;
                #pragma unroll
                for (int i = 0; i < 4; ++i)
                    #pragma unroll
                    for (int j2 = 0; j2 < 2; ++j2) {
                        MMA16816(acc[i][jj*2+j2], ah[i], bh2[j2]);
                        MMA16816(acc[i][jj*2+j2], ah[i], bl2[j2]);
                        MMA16816(acc[i][jj*2+j2], al[i], bh2[j2]);
                    }
            }
        }
        scur = (scur == NSTAGE-1) ? 0 : scur+1;
        snext2 = (snext2 == NSTAGE-1) ? 0 : snext2+1;
    }

    if (mode == 3) {
        __syncthreads();
        if (tid < 128) { s_sum[tid] = 0.f; s_sq[tid] = 0.f; }
        __syncthreads();
    }

    float psum[8] = {}, psq[8] = {};
    int rbase = m0 + wm*64 + (lane >> 2);
    int cbase = n0 + wn*32 + (lane & 3)*2;
    #pragma unroll
    for (int i = 0; i < 4; ++i) {
        #pragma unroll
        for (int j = 0; j < 4; ++j) {
            int gc = cbase + j*8;
            #pragma unroll
            for (int half = 0; half < 2; ++half) {
                long long gr = rbase + i*16 + half*8;
                float v0 = acc[i][j][half*2], v1 = acc[i][j][half*2 + 1];
                long long idx = gr * ldc + gc;
                if (mode == 2) {
                    v0 = fmaxf(v0 + bias[gc], 0.f);
                    v1 = fmaxf(v1 + bias[gc+1], 0.f);
                    split_store(Chi, Clo, idx, v0, v1);
                } else {
                    *(float2*)&Cf[idx] = make_float2(v0, v1);
                    if (mode == 3) {
                        psum[j*2]   += v0;  psq[j*2]   += v0*v0;
                        psum[j*2+1] += v1;  psq[j*2+1] += v1*v1;
                    }
                }
            }
        }
    }

    if (mode == 3) {
        int lc = wn*32 + (lane & 3)*2;
        #pragma unroll
        for (int j = 0; j < 4; ++j) {
            atomicAdd(&s_sum[lc + j*8],     psum[j*2]);
            atomicAdd(&s_sum[lc + j*8 + 1], psum[j*2+1]);
            atomicAdd(&s_sq[lc + j*8],      psq[j*2]);
            atomicAdd(&s_sq[lc + j*8 + 1],  psq[j*2+1]);
        }
        __syncthreads();
        if (tid < 128) {
            atomicAdd(&g_s2[n0 + tid],  s_sum[tid]);
            atomicAdd(&g_sq2[n0 + tid], s_sq[tid]);
        }
    }
}

// ---------------- pool / BN3 / tail ----------------
__global__ void k_pool(const float* __restrict__ g2w, const float* __restrict__ b2w) {
    int c = threadIdx.x;
    int chunk = blockIdx.x;
    int tp = blockIdx.y;
    int g = blockIdx.z;
    float mu  = g_s2[c]  * (1.f/62464.f);
    float var = g_sq2[c] * (1.f/62464.f) - mu*mu;
    float a = g2w[c] * rsqrtf(var + EPSV);
    float bb = b2w[c] - mu*a;
    float acc = 0.f;
    for (int nl = 0; nl < 16; ++nl) {
        int n = g*64 + chunk*16 + nl;
        const float* p = &g_y2[(n*122 + tp*4)*128 + c];
        float s4 = p[0] + p[128] + p[256] + p[384];
        acc += fmaxf(a * (s4 * 0.25f) + bb, 0.f);
    }
    atomicAdd(&g_gbuf[(g*30 + tp)*128 + c], acc * (1.f/64.f));
}

__global__ void k_bn3stats() {
    __shared__ float red[256];
    int tid = threadIdx.x;
    int c = tid & 127, r0 = tid >> 7;
    float ls = 0.f, lq = 0.f;
    for (int r = r0; r < 224; r += 2) { float v = g_y3[r*128 + c]; ls += v; lq += v*v; }
    red[tid] = ls; __syncthreads();
    float ssum = 0.f;
    if (tid < 128) ssum = red[tid] + red[tid+128];
    __syncthreads();
    red[tid] = lq; __syncthreads();
    if (tid < 128) {
        float q = red[tid] + red[tid+128];
        float mu = ssum * (1.f/224.f);
        float var = q * (1.f/224.f) - mu*mu;
        g_mu3[tid] = mu;
        g_rs3[tid] = rsqrtf(var + EPSV);
    }
}

__global__ void k_tail(const float* __restrict__ g3w, const float* __restrict__ b3w,
                       const float* __restrict__ Wd, const float* __restrict__ bd,
                       float* __restrict__ out) {
    __shared__ float gg[896];
    __shared__ float slog[4];
    int b = blockIdx.x, tid = threadIdx.x;
    int c = tid;
    float a = g3w[c] * g_rs3[c];
    float bb = b3w[c] - g_mu3[c]*a;
    #pragma unroll
    for (int tp = 0; tp < 7; ++tp) {
        const float* p = &g_y3[(b*28 + tp*4)*128 + c];
        float s4 = (p[0] + p[128] + p[256] + p[384]) * 0.25f;
        gg[tp*128 + c] = fmaxf(a*s4 + bb, 0.f);
    }
    __syncthreads();
    int w = tid >> 5, lane = tid & 31;
    float s = 0.f;
    for (int i = lane; i < 896; i += 32) s += gg[i] * Wd[i*4 + w];
    #pragma unroll
    for (int off = 16; off; off >>= 1) s += __shfl_xor_sync(0xffffffffu, s, off);
    if (lane == 0) slog[w] = s + bd[w];
    __syncthreads();
    if (tid == 0) {
        float m = fmaxf(fmaxf(slog[0], slog[1]), fmaxf(slog[2], slog[3]));
        float se = expf(slog[0]-m)+expf(slog[1]-m)+expf(slog[2]-m)+expf(slog[3]-m);
        float lse = logf(se);
        #pragma unroll
        for (int j = 0; j < 4; ++j) out[b*4 + j] = slog[j] - m - lse;
    }
}

// ---------------- launch ----------------
extern "C" void kernel_launch(void* const* d_in, const int* in_sizes, int n_in,
                              void* d_out, int out_size) {
    const float* x   = (const float*)d_in[0];
    const float* pos = (const float*)d_in[1];
    const int*   ei  = (const int*)d_in[2];
    const float* W1  = (const float*)d_in[4];
    const float* g1  = (const float*)d_in[5];
    const float* b1  = (const float*)d_in[6];
    const float* Wp1 = (const float*)d_in[7];
    const float* bp1 = (const float*)d_in[8];
    const float* Wp2 = (const float*)d_in[9];
    const float* bp2 = (const float*)d_in[10];
    const float* Wg1 = (const float*)d_in[11];
    const float* bg1 = (const float*)d_in[12];
    const float* Wg2 = (const float*)d_in[13];
    const float* bg2 = (const float*)d_in[14];
    const float* W2  = (const float*)d_in[15];
    const float* g2  = (const float*)d_in[16];
    const float* b2  = (const float*)d_in[17];
    const float* W3  = (const float*)d_in[18];
    const float* g3  = (const float*)d_in[19];
    const float* b3  = (const float*)d_in[20];
    const float* Wd  = (const float*)d_in[21];
    const float* bd  = (const float*)d_in[22];
    float* out = (float*)d_out;

    float *pY2, *pGbuf, *pY3;
    __nv_bfloat16 *pH0h, *pH0l, *pA0h, *pA0l, *pH1h, *pH1l, *pA1h, *pA1l, *pH2h, *pH2l;
    __nv_bfloat16 *pWg1h, *pWg1l, *pWg2h, *pWg2l, *pW2h, *pW2l;
    cudaGetSymbolAddress((void**)&pY2,   g_y2);
    cudaGetSymbolAddress((void**)&pGbuf, g_gbuf);
    cudaGetSymbolAddress((void**)&pY3,   g_y3);
    cudaGetSymbolAddress((void**)&pH0h,  g_h0h);
    cudaGetSymbolAddress((void**)&pH0l,  g_h0l);
    cudaGetSymbolAddress((void**)&pA0h,  g_agg0h);
    cudaGetSymbolAddress((void**)&pA0l,  g_agg0l);
    cudaGetSymbolAddress((void**)&pH1h,  g_h1h);
    cudaGetSymbolAddress((void**)&pH1l,  g_h1l);
    cudaGetSymbolAddress((void**)&pA1h,  g_agg1h);
    cudaGetSymbolAddress((void**)&pA1l,  g_agg1l);
    cudaGetSymbolAddress((void**)&pH2h,  g_h2h);
    cudaGetSymbolAddress((void**)&pH2l,  g_h2l);
    cudaGetSymbolAddress((void**)&pWg1h, g_Wg1th);
    cudaGetSymbolAddress((void**)&pWg1l, g_Wg1tl);
    cudaGetSymbolAddress((void**)&pWg2h, g_Wg2th);
    cudaGetSymbolAddress((void**)&pWg2l, g_Wg2tl);
    cudaGetSymbolAddress((void**)&pW2h,  g_W2th);
    cudaGetSymbolAddress((void**)&pW2l,  g_W2tl);

    const int DSM = NSTAGE*STAGE_BYTES;   // 98304
    cudaFuncSetAttribute(k_gemm_tc, cudaFuncAttributeMaxDynamicSharedMemorySize, DSM);
    cudaFuncSetAttribute(k_agg_tc, cudaFuncAttributeMaxDynamicSharedMemorySize, AGG_SMEM);

    k_zero<<<128, 256>>>();
    k_deg<<<16, 256>>>(ei);
    k_adj<<<18, 256>>>(ei);
    k_wprep<<<1344, 256>>>(Wg1, Wg2, W2);
    k_pe<<<512, 64>>>(pos, Wp1, bp1, Wp2, bp2);
    k_conv1stats<<<1024, 256>>>(x, W1);
    k_bn1pe<<<1024, 256>>>(x, W1, g1, b1);

    // agg0 = A @ h0  (TC, split out), F = T*C0 = 8192
    k_agg_tc<<<dim3(32, 8), 256, AGG_SMEM>>>(pH0h, pH0l, pA0h, pA0l, 8192);
    // gcn1: h1 = relu(agg0 @ Wg1^T + bg1)  (TC, split out)
    k_gemm_tc<<<dim3(2, 512), 256, DSM>>>(pA0h, pA0l, pWg1h, pWg1l, bg1,
                                          nullptr, pH1h, pH1l,
                                          64, 65536, 65536, 64, 256, 2);
    // agg1 = A @ h1  (TC, split out), F = T*EMB = 32768
    k_agg_tc<<<dim3(128, 8), 256, AGG_SMEM>>>(pH1h, pH1l, pA1h, pA1l, 32768);
    // gcn2: h2 = relu(agg1 @ Wg2^T + bg2)  (TC, split out)
    k_gemm_tc<<<dim3(2, 512), 256, DSM>>>(pA1h, pA1l, pWg2h, pWg2l, bg2,
                                          nullptr, pH2h, pH2l,
                                          256, 65536, 65536, 256, 256, 2);
    // conv2 (k=7 VALID, 256->128) implicit GEMM (TC, fp32 out + fused BN2 stats)
    k_gemm_tc<<<dim3(1, 488), 256, DSM>>>(pH2h, pH2l, pW2h, pW2l, nullptr,
                                          pY2, nullptr, nullptr,
                                          1792, 122, 128, 256, 128, 3);
    k_pool<<<dim3(4, 30, 8), 128>>>(g2, b2);
    // conv3 (k=3 VALID, 128->128) SIMT
    k_gemm<<<dim3(2, 4, 1), 256>>>(pGbuf, W3, pY3, 224, 128, 384, 28, 30, 128);
    k_bn3stats<<<1, 256>>>();
    k_tail<<<8, 128>>>(g3, b3, Wd, bd, out);
}